// round 1
// baseline (speedup 1.0000x reference)
#include <cuda_runtime.h>

#define GN 50000
#define GE 800000
#define EP 850000   // GE + GN self-loops
#define GG 64

// ---------------- scratch (device globals; no allocation) ----------------
__device__ __align__(16) float    d_xl[GN * 128];
__device__ __align__(16) float    d_xr[GN * 128];
__device__ __align__(16) float    d_h[GN * 128];
__device__ __align__(16) float    d_accum[GN * 128];
__device__ __align__(16) float    d_logit[EP * 4];     // logits, then ex
__device__ __align__(16) unsigned d_amax_u[GN * 4];
__device__ __align__(16) float    d_amax[GN * 4];
__device__ __align__(16) float    d_denom[GN * 4];
__device__ int   d_src[EP];
__device__ int   d_dst[EP];
__device__ float d_pool[GG * 128];
__device__ float d_cnt[GG];
__device__ int   d_is64;

// ---------------- int32/int64 width detection ----------------
// If edge_index is int64 (little-endian, values < 2^31), every odd 32-bit word
// is 0. If int32, odd words are random node ids in [0,50000) -> ~never all 0.
__global__ void detect_kernel(const int* __restrict__ ei32) {
    if (threadIdx.x == 0 && blockIdx.x == 0) {
        int any = 0;
        #pragma unroll
        for (int i = 1; i < 128; i += 2) any |= ei32[i];
        d_is64 = (any == 0) ? 1 : 0;
    }
}

__global__ void convert_kernel(const void* __restrict__ ei) {
    int i = blockIdx.x * blockDim.x + threadIdx.x;
    if (i >= EP) return;
    if (i < GE) {
        if (d_is64) {
            const long long* p = (const long long*)ei;
            d_src[i] = (int)p[i];
            d_dst[i] = (int)p[GE + i];
        } else {
            const int* p = (const int*)ei;
            d_src[i] = p[i];
            d_dst[i] = p[GE + i];
        }
    } else {
        d_src[i] = i - GE;
        d_dst[i] = i - GE;
    }
}

// ---------------- zeroing ----------------
__global__ void zero_layer_kernel() {
    int i = blockIdx.x * blockDim.x + threadIdx.x;
    if (i < GN * 128) d_accum[i] = 0.f;
    if (i < GN * 4) { d_amax_u[i] = 0u; d_denom[i] = 0.f; }
}

__global__ void zero_pool_kernel() {
    int i = blockIdx.x * blockDim.x + threadIdx.x;
    if (i < GG * 128) d_pool[i] = 0.f;
    if (i < GG) d_cnt[i] = 0.f;
}

// ---------------- GEMM: xl = A@Wl^T + bl ; xr = A@Wr^T + br ----------------
// A: [GN,128] (x input or d_h). W: [128,128] row-major (out,in).
// 64x64 tile, 4x4 per-thread microtile, K chunked by 16, transposed smem tiles.
__global__ void __launch_bounds__(256) gemm_kernel(
    const float* __restrict__ x_in,
    const float* __restrict__ Wl, const float* __restrict__ bl,
    const float* __restrict__ Wr, const float* __restrict__ br,
    int use_h)
{
    const float* A = use_h ? d_h : x_in;
    int mat  = blockIdx.y >> 1;
    int col0 = (blockIdx.y & 1) * 64;
    const float* W    = mat ? Wr : Wl;
    const float* bias = mat ? br : bl;
    float* O          = mat ? d_xr : d_xl;
    int row0 = blockIdx.x * 64;

    __shared__ float As[16][68];
    __shared__ float Bs[16][68];

    int tid = threadIdx.x;
    int tr = tid >> 4, tc = tid & 15;
    int lk = tid & 15;      // k within chunk
    int lr = tid >> 4;      // row base for loads

    float acc[4][4] = {};

    for (int kc = 0; kc < 128; kc += 16) {
        #pragma unroll
        for (int p = 0; p < 4; p++) {
            int r  = lr + p * 16;
            int gr = row0 + r;
            As[lk][r] = (gr < GN) ? A[gr * 128 + kc + lk] : 0.f;
            Bs[lk][r] = W[(col0 + r) * 128 + kc + lk];
        }
        __syncthreads();
        #pragma unroll
        for (int k = 0; k < 16; k++) {
            float4 a = *(const float4*)&As[k][tr * 4];
            float4 b = *(const float4*)&Bs[k][tc * 4];
            acc[0][0] += a.x * b.x; acc[0][1] += a.x * b.y; acc[0][2] += a.x * b.z; acc[0][3] += a.x * b.w;
            acc[1][0] += a.y * b.x; acc[1][1] += a.y * b.y; acc[1][2] += a.y * b.z; acc[1][3] += a.y * b.w;
            acc[2][0] += a.z * b.x; acc[2][1] += a.z * b.y; acc[2][2] += a.z * b.z; acc[2][3] += a.z * b.w;
            acc[3][0] += a.w * b.x; acc[3][1] += a.w * b.y; acc[3][2] += a.w * b.z; acc[3][3] += a.w * b.w;
        }
        __syncthreads();
    }

    #pragma unroll
    for (int i = 0; i < 4; i++) {
        int gr = row0 + tr * 4 + i;
        if (gr < GN) {
            int c = col0 + tc * 4;
            float4 o;
            o.x = acc[i][0] + bias[c + 0];
            o.y = acc[i][1] + bias[c + 1];
            o.z = acc[i][2] + bias[c + 2];
            o.w = acc[i][3] + bias[c + 3];
            *(float4*)&O[gr * 128 + c] = o;
        }
    }
}

// ---------------- pass A: edge logits + segment max ----------------
__device__ __forceinline__ unsigned enc_f(float f) {
    unsigned u = __float_as_uint(f);
    return (u & 0x80000000u) ? ~u : (u | 0x80000000u);
}

__global__ void __launch_bounds__(256) edge_logits_kernel(const float* __restrict__ att) {
    int e = blockIdx.x * 8 + (threadIdx.x >> 5);
    if (e >= EP) return;
    int lane = threadIdx.x & 31;
    int s = d_src[e], d = d_dst[e];
    const float* pl = d_xl + (size_t)s * 128;
    const float* pr = d_xr + (size_t)d * 128;
    float a0, a1, a2, a3;
    {
        float v;
        v = pl[lane]      + pr[lane];      v = v > 0.f ? v : 0.2f * v; a0 = v * att[lane];
        v = pl[32 + lane] + pr[32 + lane]; v = v > 0.f ? v : 0.2f * v; a1 = v * att[32 + lane];
        v = pl[64 + lane] + pr[64 + lane]; v = v > 0.f ? v : 0.2f * v; a2 = v * att[64 + lane];
        v = pl[96 + lane] + pr[96 + lane]; v = v > 0.f ? v : 0.2f * v; a3 = v * att[96 + lane];
    }
    #pragma unroll
    for (int off = 16; off; off >>= 1) {
        a0 += __shfl_xor_sync(0xffffffffu, a0, off);
        a1 += __shfl_xor_sync(0xffffffffu, a1, off);
        a2 += __shfl_xor_sync(0xffffffffu, a2, off);
        a3 += __shfl_xor_sync(0xffffffffu, a3, off);
    }
    if (lane < 4) {
        float lg = (lane & 2) ? ((lane & 1) ? a3 : a2) : ((lane & 1) ? a1 : a0);
        d_logit[e * 4 + lane] = lg;
        atomicMax(&d_amax_u[d * 4 + lane], enc_f(lg));
    }
}

__global__ void decode_amax_kernel() {
    int i = blockIdx.x * blockDim.x + threadIdx.x;
    if (i >= GN * 4) return;
    unsigned k = d_amax_u[i];
    unsigned u = (k & 0x80000000u) ? (k ^ 0x80000000u) : ~k;
    d_amax[i] = __uint_as_float(u);
}

// ---------------- pass B: exp + denom ----------------
__global__ void edge_exp_kernel() {
    int e = blockIdx.x * blockDim.x + threadIdx.x;
    if (e >= EP) return;
    int d = d_dst[e];
    float4 lg = ((const float4*)d_logit)[e];
    float4 am = ((const float4*)d_amax)[d];
    float4 ex;
    ex.x = __expf(lg.x - am.x);
    ex.y = __expf(lg.y - am.y);
    ex.z = __expf(lg.z - am.z);
    ex.w = __expf(lg.w - am.w);
    ((float4*)d_logit)[e] = ex;
    atomicAdd(&d_denom[d * 4 + 0], ex.x);
    atomicAdd(&d_denom[d * 4 + 1], ex.y);
    atomicAdd(&d_denom[d * 4 + 2], ex.z);
    atomicAdd(&d_denom[d * 4 + 3], ex.w);
}

// ---------------- pass C: alpha-weighted scatter ----------------
__global__ void __launch_bounds__(256) edge_aggregate_kernel() {
    int e = blockIdx.x * 8 + (threadIdx.x >> 5);
    if (e >= EP) return;
    int lane = threadIdx.x & 31;
    int s = d_src[e], d = d_dst[e];
    float a = 0.f;
    if (lane < 4) a = d_logit[e * 4 + lane] / d_denom[d * 4 + lane];
    float a0 = __shfl_sync(0xffffffffu, a, 0);
    float a1 = __shfl_sync(0xffffffffu, a, 1);
    float a2 = __shfl_sync(0xffffffffu, a, 2);
    float a3 = __shfl_sync(0xffffffffu, a, 3);
    const float* pl = d_xl + (size_t)s * 128;
    float* po = d_accum + (size_t)d * 128;
    atomicAdd(&po[lane],      a0 * pl[lane]);
    atomicAdd(&po[32 + lane], a1 * pl[32 + lane]);
    atomicAdd(&po[64 + lane], a2 * pl[64 + lane]);
    atomicAdd(&po[96 + lane], a3 * pl[96 + lane]);
}

// ---------------- bias + relu ----------------
__global__ void finish_kernel(const float* __restrict__ bias) {
    int i = blockIdx.x * blockDim.x + threadIdx.x;
    if (i >= GN * 128) return;
    d_h[i] = fmaxf(d_accum[i] + bias[i & 127], 0.f);
}

// ---------------- pooling (batch sorted -> register accumulation) ----------------
__global__ void count_kernel(const void* __restrict__ batch) {
    int i = blockIdx.x * blockDim.x + threadIdx.x;
    if (i >= GN) return;
    int g = d_is64 ? (int)((const long long*)batch)[i] : ((const int*)batch)[i];
    atomicAdd(&d_cnt[g], 1.f);
}

__global__ void pool_kernel(const void* __restrict__ batch) {
    const int CHUNK = 256;
    int n0 = blockIdx.x * CHUNK;
    int n1 = n0 + CHUNK; if (n1 > GN) n1 = GN;
    int col = threadIdx.x;
    int is64 = d_is64;
    int curg = -1;
    float acc = 0.f;
    for (int n = n0; n < n1; n++) {
        int g = is64 ? (int)((const long long*)batch)[n] : ((const int*)batch)[n];
        if (g != curg) {
            if (curg >= 0) atomicAdd(&d_pool[curg * 128 + col], acc);
            curg = g; acc = 0.f;
        }
        acc += d_h[n * 128 + col];
    }
    if (curg >= 0) atomicAdd(&d_pool[curg * 128 + col], acc);
}

// ---------------- classifier ----------------
__global__ void classifier_kernel(
    const float* __restrict__ Wc1, const float* __restrict__ bc1,
    const float* __restrict__ Wc2, const float* __restrict__ bc2,
    float* __restrict__ out)
{
    int g = threadIdx.x;
    if (g >= GG) return;
    float inv = 1.f / fmaxf(d_cnt[g], 1.f);
    float z[8];
    #pragma unroll
    for (int j = 0; j < 8; j++) {
        float s = 0.f;
        for (int k = 0; k < 128; k++)
            s += d_pool[g * 128 + k] * Wc1[j * 128 + k];
        s = s * inv + bc1[j];
        z[j] = fmaxf(s, 0.f);
    }
    float o = bc2[0];
    #pragma unroll
    for (int j = 0; j < 8; j++) o += z[j] * Wc2[j];
    out[g] = o;
}

// ---------------- launch ----------------
extern "C" void kernel_launch(void* const* d_in, const int* in_sizes, int n_in,
                              void* d_out, int out_size) {
    const float* x     = (const float*)d_in[0];
    const void*  ei    = d_in[1];
    const void*  batch = d_in[2];
    const float* Wl0 = (const float*)d_in[3];
    const float* bl0 = (const float*)d_in[4];
    const float* Wr0 = (const float*)d_in[5];
    const float* br0 = (const float*)d_in[6];
    const float* at0 = (const float*)d_in[7];
    const float* bi0 = (const float*)d_in[8];
    const float* Wl1 = (const float*)d_in[9];
    const float* bl1 = (const float*)d_in[10];
    const float* Wr1 = (const float*)d_in[11];
    const float* br1 = (const float*)d_in[12];
    const float* at1 = (const float*)d_in[13];
    const float* bi1 = (const float*)d_in[14];
    const float* Wc1 = (const float*)d_in[15];
    const float* bc1 = (const float*)d_in[16];
    const float* Wc2 = (const float*)d_in[17];
    const float* bc2 = (const float*)d_in[18];
    float* out = (float*)d_out;

    detect_kernel<<<1, 32>>>((const int*)ei);
    convert_kernel<<<(EP + 255) / 256, 256>>>(ei);

    const int NB_NODE = (GN * 128 + 255) / 256;
    const int NB_EDGE_W = (EP + 7) / 8;      // warp per edge
    const int NB_EDGE_T = (EP + 255) / 256;  // thread per edge

    for (int layer = 0; layer < 2; layer++) {
        const float* Wl = layer ? Wl1 : Wl0;
        const float* bl = layer ? bl1 : bl0;
        const float* Wr = layer ? Wr1 : Wr0;
        const float* br = layer ? br1 : br0;
        const float* at = layer ? at1 : at0;
        const float* bi = layer ? bi1 : bi0;

        zero_layer_kernel<<<NB_NODE, 256>>>();
        gemm_kernel<<<dim3((GN + 63) / 64, 4), 256>>>(x, Wl, bl, Wr, br, layer);
        edge_logits_kernel<<<NB_EDGE_W, 256>>>(at);
        decode_amax_kernel<<<(GN * 4 + 255) / 256, 256>>>();
        edge_exp_kernel<<<NB_EDGE_T, 256>>>();
        edge_aggregate_kernel<<<NB_EDGE_W, 256>>>();
        finish_kernel<<<NB_NODE, 256>>>(bi);
    }

    zero_pool_kernel<<<(GG * 128 + 255) / 256, 256>>>();
    count_kernel<<<(GN + 255) / 256, 256>>>(batch);
    pool_kernel<<<(GN + 255) / 256, 128>>>(batch);
    classifier_kernel<<<1, 64>>>(Wc1, bc1, Wc2, bc2, out);
}

// round 2
// speedup vs baseline: 1.4636x; 1.4636x over previous
#include <cuda_runtime.h>

#define GN 50000
#define GE 800000
#define EP 850000   // GE + GN self-loops
#define GG 64
#define NCH 98      // ceil(GN/512)

// ---------------- scratch (device globals; no allocation) ----------------
__device__ __align__(16) float d_xl[GN * 128];
__device__ __align__(16) float d_xr[GN * 128];
__device__ __align__(16) float d_h[GN * 128];
__device__ int   d_src[EP];
__device__ int   d_dst[EP];
__device__ int   d_rowcnt[GN];
__device__ int   d_rowstart[GN + 1];
__device__ int   d_rowfill[GN];
__device__ int   d_csrsrc[EP];
__device__ int   d_chunksum[NCH];
__device__ float d_pool[GG * 128];
__device__ float d_cnt[GG];
__device__ int   d_is64;

// ---------------- int32/int64 width detection ----------------
__global__ void detect_kernel(const int* __restrict__ ei32) {
    if (threadIdx.x == 0 && blockIdx.x == 0) {
        int any = 0;
        #pragma unroll
        for (int i = 1; i < 128; i += 2) any |= ei32[i];
        d_is64 = (any == 0) ? 1 : 0;
    }
}

__global__ void convert_kernel(const void* __restrict__ ei) {
    int i = blockIdx.x * blockDim.x + threadIdx.x;
    if (i >= EP) return;
    if (i < GE) {
        if (d_is64) {
            const long long* p = (const long long*)ei;
            d_src[i] = (int)p[i];
            d_dst[i] = (int)p[GE + i];
        } else {
            const int* p = (const int*)ei;
            d_src[i] = p[i];
            d_dst[i] = p[GE + i];
        }
    } else {
        d_src[i] = i - GE;
        d_dst[i] = i - GE;
    }
}

// ---------------- CSR build: hist -> scan -> scatter ----------------
__global__ void zero_cnt_kernel() {
    int i = blockIdx.x * blockDim.x + threadIdx.x;
    if (i < GN) d_rowcnt[i] = 0;
}

__global__ void hist_kernel() {
    int i = blockIdx.x * blockDim.x + threadIdx.x;
    if (i < EP) atomicAdd(&d_rowcnt[d_dst[i]], 1);
}

__global__ void chunk_sum_kernel() {
    __shared__ int sh[256];
    int b = blockIdx.x, t = threadIdx.x;
    int base = b * 512;
    int v = 0;
    int i0 = base + t;       if (i0 < GN) v += d_rowcnt[i0];
    int i1 = base + 256 + t; if (i1 < GN) v += d_rowcnt[i1];
    sh[t] = v; __syncthreads();
    for (int off = 128; off; off >>= 1) {
        if (t < off) sh[t] += sh[t + off];
        __syncthreads();
    }
    if (t == 0) d_chunksum[b] = sh[0];
}

__global__ void tops_kernel() {
    if (threadIdx.x == 0) {
        int run = 0;
        for (int b = 0; b < NCH; b++) { int t = d_chunksum[b]; d_chunksum[b] = run; run += t; }
        d_rowstart[GN] = EP;
    }
}

__global__ void scan_apply_kernel() {
    __shared__ int sh[512];
    int b = blockIdx.x, t = threadIdx.x;
    int i = b * 512 + t;
    int v = (i < GN) ? d_rowcnt[i] : 0;
    sh[t] = v; __syncthreads();
    for (int off = 1; off < 512; off <<= 1) {
        int a = (t >= off) ? sh[t - off] : 0;
        __syncthreads();
        sh[t] += a;
        __syncthreads();
    }
    if (i < GN) {
        int excl = sh[t] - v + d_chunksum[b];
        d_rowstart[i] = excl;
        d_rowfill[i]  = excl;
    }
}

__global__ void scatter_kernel() {
    int i = blockIdx.x * blockDim.x + threadIdx.x;
    if (i >= EP) return;
    int dd = d_dst[i];
    int pos = atomicAdd(&d_rowfill[dd], 1);
    d_csrsrc[pos] = d_src[i];
}

// ---------------- GEMM: xl = A@Wl^T + bl ; xr = A@Wr^T + br ----------------
__global__ void __launch_bounds__(256) gemm_kernel(
    const float* __restrict__ x_in,
    const float* __restrict__ Wl, const float* __restrict__ bl,
    const float* __restrict__ Wr, const float* __restrict__ br,
    int use_h)
{
    const float* A = use_h ? d_h : x_in;
    int mat  = blockIdx.y >> 1;
    int col0 = (blockIdx.y & 1) * 64;
    const float* W    = mat ? Wr : Wl;
    const float* bias = mat ? br : bl;
    float* O          = mat ? d_xr : d_xl;
    int row0 = blockIdx.x * 64;

    __shared__ float As[16][68];
    __shared__ float Bs[16][68];

    int tid = threadIdx.x;
    int tr = tid >> 4, tc = tid & 15;
    int lk = tid & 15;
    int lr = tid >> 4;

    float acc[4][4] = {};

    for (int kc = 0; kc < 128; kc += 16) {
        #pragma unroll
        for (int p = 0; p < 4; p++) {
            int r  = lr + p * 16;
            int gr = row0 + r;
            As[lk][r] = (gr < GN) ? A[gr * 128 + kc + lk] : 0.f;
            Bs[lk][r] = W[(col0 + r) * 128 + kc + lk];
        }
        __syncthreads();
        #pragma unroll
        for (int k = 0; k < 16; k++) {
            float4 a = *(const float4*)&As[k][tr * 4];
            float4 b = *(const float4*)&Bs[k][tc * 4];
            acc[0][0] += a.x * b.x; acc[0][1] += a.x * b.y; acc[0][2] += a.x * b.z; acc[0][3] += a.x * b.w;
            acc[1][0] += a.y * b.x; acc[1][1] += a.y * b.y; acc[1][2] += a.y * b.z; acc[1][3] += a.y * b.w;
            acc[2][0] += a.z * b.x; acc[2][1] += a.z * b.y; acc[2][2] += a.z * b.z; acc[2][3] += a.z * b.w;
            acc[3][0] += a.w * b.x; acc[3][1] += a.w * b.y; acc[3][2] += a.w * b.z; acc[3][3] += a.w * b.w;
        }
        __syncthreads();
    }

    #pragma unroll
    for (int i = 0; i < 4; i++) {
        int gr = row0 + tr * 4 + i;
        if (gr < GN) {
            int c = col0 + tc * 4;
            float4 o;
            o.x = acc[i][0] + bias[c + 0];
            o.y = acc[i][1] + bias[c + 1];
            o.z = acc[i][2] + bias[c + 2];
            o.w = acc[i][3] + bias[c + 3];
            *(float4*)&O[gr * 128 + c] = o;
        }
    }
}

// ---------------- fused GATv2 softmax + aggregation (warp per dst row) ----------------
__device__ __forceinline__ void online_update(float lg, float xv,
                                              float& mx, float& dn, float& ac) {
    if (lg > mx) {
        float sc = __expf(mx - lg);
        dn *= sc; ac *= sc; mx = lg;
    }
    float w = __expf(lg - mx);
    dn += w; ac += w * xv;
}

__global__ void __launch_bounds__(256) gat_row_kernel(const float* __restrict__ att,
                                                      const float* __restrict__ bias)
{
    int row = blockIdx.x * 8 + (threadIdx.x >> 5);
    if (row >= GN) return;
    int lane = threadIdx.x & 31;

    float at0 = att[lane],      at1 = att[32 + lane];
    float at2 = att[64 + lane], at3 = att[96 + lane];
    const float* pr = d_xr + (size_t)row * 128;
    float xr0 = pr[lane],      xr1 = pr[32 + lane];
    float xr2 = pr[64 + lane], xr3 = pr[96 + lane];

    int e0 = d_rowstart[row], e1 = d_rowstart[row + 1];

    float mx0 = -1e30f, mx1 = -1e30f, mx2 = -1e30f, mx3 = -1e30f;
    float dn0 = 0.f, dn1 = 0.f, dn2 = 0.f, dn3 = 0.f;
    float ac0 = 0.f, ac1 = 0.f, ac2 = 0.f, ac3 = 0.f;

    int s = (e0 < e1) ? d_csrsrc[e0] : 0;
    for (int j = e0; j < e1; j++) {
        int s_next = (j + 1 < e1) ? d_csrsrc[j + 1] : 0;
        const float* pl = d_xl + (size_t)s * 128;
        float x0 = pl[lane],      x1 = pl[32 + lane];
        float x2 = pl[64 + lane], x3 = pl[96 + lane];

        float v, l0, l1, l2, l3;
        v = x0 + xr0; v = v > 0.f ? v : 0.2f * v; l0 = v * at0;
        v = x1 + xr1; v = v > 0.f ? v : 0.2f * v; l1 = v * at1;
        v = x2 + xr2; v = v > 0.f ? v : 0.2f * v; l2 = v * at2;
        v = x3 + xr3; v = v > 0.f ? v : 0.2f * v; l3 = v * at3;
        #pragma unroll
        for (int off = 16; off; off >>= 1) {
            l0 += __shfl_xor_sync(0xffffffffu, l0, off);
            l1 += __shfl_xor_sync(0xffffffffu, l1, off);
            l2 += __shfl_xor_sync(0xffffffffu, l2, off);
            l3 += __shfl_xor_sync(0xffffffffu, l3, off);
        }
        online_update(l0, x0, mx0, dn0, ac0);
        online_update(l1, x1, mx1, dn1, ac1);
        online_update(l2, x2, mx2, dn2, ac2);
        online_update(l3, x3, mx3, dn3, ac3);
        s = s_next;
    }

    float* po = d_h + (size_t)row * 128;
    po[lane]      = fmaxf(ac0 / dn0 + bias[lane],      0.f);
    po[32 + lane] = fmaxf(ac1 / dn1 + bias[32 + lane], 0.f);
    po[64 + lane] = fmaxf(ac2 / dn2 + bias[64 + lane], 0.f);
    po[96 + lane] = fmaxf(ac3 / dn3 + bias[96 + lane], 0.f);
}

// ---------------- pooling ----------------
__global__ void zero_pool_kernel() {
    int i = blockIdx.x * blockDim.x + threadIdx.x;
    if (i < GG * 128) d_pool[i] = 0.f;
    if (i < GG) d_cnt[i] = 0.f;
}

__global__ void count_kernel(const void* __restrict__ batch) {
    int i = blockIdx.x * blockDim.x + threadIdx.x;
    if (i >= GN) return;
    int g = d_is64 ? (int)((const long long*)batch)[i] : ((const int*)batch)[i];
    atomicAdd(&d_cnt[g], 1.f);
}

__global__ void pool_kernel(const void* __restrict__ batch) {
    const int CHUNK = 256;
    int n0 = blockIdx.x * CHUNK;
    int n1 = n0 + CHUNK; if (n1 > GN) n1 = GN;
    int col = threadIdx.x;
    int is64 = d_is64;
    int curg = -1;
    float acc = 0.f;
    for (int n = n0; n < n1; n++) {
        int g = is64 ? (int)((const long long*)batch)[n] : ((const int*)batch)[n];
        if (g != curg) {
            if (curg >= 0) atomicAdd(&d_pool[curg * 128 + col], acc);
            curg = g; acc = 0.f;
        }
        acc += d_h[n * 128 + col];
    }
    if (curg >= 0) atomicAdd(&d_pool[curg * 128 + col], acc);
}

// ---------------- classifier ----------------
__global__ void classifier_kernel(
    const float* __restrict__ Wc1, const float* __restrict__ bc1,
    const float* __restrict__ Wc2, const float* __restrict__ bc2,
    float* __restrict__ out)
{
    int g = threadIdx.x;
    if (g >= GG) return;
    float inv = 1.f / fmaxf(d_cnt[g], 1.f);
    float z[8];
    #pragma unroll
    for (int j = 0; j < 8; j++) {
        float s = 0.f;
        for (int k = 0; k < 128; k++)
            s += d_pool[g * 128 + k] * Wc1[j * 128 + k];
        s = s * inv + bc1[j];
        z[j] = fmaxf(s, 0.f);
    }
    float o = bc2[0];
    #pragma unroll
    for (int j = 0; j < 8; j++) o += z[j] * Wc2[j];
    out[g] = o;
}

// ---------------- launch ----------------
extern "C" void kernel_launch(void* const* d_in, const int* in_sizes, int n_in,
                              void* d_out, int out_size) {
    const float* x     = (const float*)d_in[0];
    const void*  ei    = d_in[1];
    const void*  batch = d_in[2];
    const float* Wl0 = (const float*)d_in[3];
    const float* bl0 = (const float*)d_in[4];
    const float* Wr0 = (const float*)d_in[5];
    const float* br0 = (const float*)d_in[6];
    const float* at0 = (const float*)d_in[7];
    const float* bi0 = (const float*)d_in[8];
    const float* Wl1 = (const float*)d_in[9];
    const float* bl1 = (const float*)d_in[10];
    const float* Wr1 = (const float*)d_in[11];
    const float* br1 = (const float*)d_in[12];
    const float* at1 = (const float*)d_in[13];
    const float* bi1 = (const float*)d_in[14];
    const float* Wc1 = (const float*)d_in[15];
    const float* bc1 = (const float*)d_in[16];
    const float* Wc2 = (const float*)d_in[17];
    const float* bc2 = (const float*)d_in[18];
    float* out = (float*)d_out;

    detect_kernel<<<1, 32>>>((const int*)ei);
    convert_kernel<<<(EP + 255) / 256, 256>>>(ei);

    // CSR build (dst-sorted), reused by both layers
    zero_cnt_kernel<<<(GN + 255) / 256, 256>>>();
    hist_kernel<<<(EP + 255) / 256, 256>>>();
    chunk_sum_kernel<<<NCH, 256>>>();
    tops_kernel<<<1, 32>>>();
    scan_apply_kernel<<<NCH, 512>>>();
    scatter_kernel<<<(EP + 255) / 256, 256>>>();

    for (int layer = 0; layer < 2; layer++) {
        const float* Wl = layer ? Wl1 : Wl0;
        const float* bl = layer ? bl1 : bl0;
        const float* Wr = layer ? Wr1 : Wr0;
        const float* br = layer ? br1 : br0;
        const float* at = layer ? at1 : at0;
        const float* bi = layer ? bi1 : bi0;

        gemm_kernel<<<dim3((GN + 63) / 64, 4), 256>>>(x, Wl, bl, Wr, br, layer);
        gat_row_kernel<<<(GN + 7) / 8, 256>>>(at, bi);
    }

    zero_pool_kernel<<<(GG * 128 + 255) / 256, 256>>>();
    count_kernel<<<(GN + 255) / 256, 256>>>(batch);
    pool_kernel<<<(GN + 255) / 256, 128>>>(batch);
    classifier_kernel<<<1, 64>>>(Wc1, bc1, Wc2, bc2, out);
}

// round 4
// speedup vs baseline: 1.5868x; 1.0842x over previous
#include <cuda_runtime.h>

#define GN 50000
#define GE 800000
#define EP 850000   // GE + GN self-loops
#define GG 64
#define NCH 98      // ceil(GN/512)

// ---------------- scratch (device globals; no allocation) ----------------
__device__ __align__(16) float d_xl[GN * 128];
__device__ __align__(16) float d_xr[GN * 128];
__device__ __align__(16) float d_h[GN * 128];
__device__ int   d_rowcnt[GN];
__device__ int   d_rowstart[GN + 1];
__device__ int   d_rowfill[GN];
__device__ int   d_csrsrc[EP];
__device__ int   d_chunksum[NCH];
__device__ float d_pool[GG * 128];
__device__ float d_cnt[GG];
__device__ int   d_is64;

// ---------------- int32/int64 width detection ----------------
__global__ void detect_kernel(const int* __restrict__ ei32) {
    if (threadIdx.x == 0 && blockIdx.x == 0) {
        int any = 0;
        #pragma unroll
        for (int i = 1; i < 128; i += 2) any |= ei32[i];
        d_is64 = (any == 0) ? 1 : 0;
    }
}

__device__ __forceinline__ int edge_at(const void* ei, int idx, int is64) {
    return is64 ? (int)((const long long*)ei)[idx] : ((const int*)ei)[idx];
}

// ---------------- CSR build: hist -> scan -> scatter ----------------
__global__ void zero_cnt_kernel() {
    int i = blockIdx.x * blockDim.x + threadIdx.x;
    if (i < GN) d_rowcnt[i] = 0;
}

__global__ void hist_kernel(const void* __restrict__ ei) {
    int i = blockIdx.x * blockDim.x + threadIdx.x;
    if (i >= EP) return;
    int dd = (i < GE) ? edge_at(ei, GE + i, d_is64) : (i - GE);
    atomicAdd(&d_rowcnt[dd], 1);
}

__global__ void chunk_sum_kernel() {
    __shared__ int sh[256];
    int b = blockIdx.x, t = threadIdx.x;
    int base = b * 512;
    int v = 0;
    int i0 = base + t;       if (i0 < GN) v += d_rowcnt[i0];
    int i1 = base + 256 + t; if (i1 < GN) v += d_rowcnt[i1];
    sh[t] = v; __syncthreads();
    for (int off = 128; off; off >>= 1) {
        if (t < off) sh[t] += sh[t + off];
        __syncthreads();
    }
    if (t == 0) d_chunksum[b] = sh[0];
}

__global__ void tops_kernel() {
    if (threadIdx.x == 0) {
        int run = 0;
        for (int b = 0; b < NCH; b++) { int t = d_chunksum[b]; d_chunksum[b] = run; run += t; }
        d_rowstart[GN] = EP;
    }
}

__global__ void scan_apply_kernel() {
    __shared__ int sh[512];
    int b = blockIdx.x, t = threadIdx.x;
    int i = b * 512 + t;
    int v = (i < GN) ? d_rowcnt[i] : 0;
    sh[t] = v; __syncthreads();
    for (int off = 1; off < 512; off <<= 1) {
        int a = (t >= off) ? sh[t - off] : 0;
        __syncthreads();
        sh[t] += a;
        __syncthreads();
    }
    if (i < GN) {
        int excl = sh[t] - v + d_chunksum[b];
        d_rowstart[i] = excl;
        d_rowfill[i]  = excl;
    }
}

__global__ void scatter_kernel(const void* __restrict__ ei) {
    int i = blockIdx.x * blockDim.x + threadIdx.x;
    if (i >= EP) return;
    int is64 = d_is64;
    int ss, dd;
    if (i < GE) { ss = edge_at(ei, i, is64); dd = edge_at(ei, GE + i, is64); }
    else        { ss = i - GE; dd = ss; }
    int pos = atomicAdd(&d_rowfill[dd], 1);
    d_csrsrc[pos] = ss;
}

// ---------------- GEMM with packed f32x2 FFMA ----------------
// xl = A@Wl^T + bl ; xr = A@Wr^T + br. A:[GN,128]. W:[128,128] (out,in).
// 64x64 tile, 4x4 microtile, K paired even/odd into f32x2 lanes.
__device__ __forceinline__ void ffma2(unsigned long long& d,
                                      unsigned long long a,
                                      unsigned long long b) {
    asm("fma.rn.f32x2 %0, %1, %2, %0;" : "+l"(d) : "l"(a), "l"(b));
}
__device__ __forceinline__ float lo32(unsigned long long v) {
    return __uint_as_float((unsigned)(v & 0xffffffffull));
}
__device__ __forceinline__ float hi32(unsigned long long v) {
    return __uint_as_float((unsigned)(v >> 32));
}

#define APITCH 20

__global__ void __launch_bounds__(256) gemm_kernel(
    const float* __restrict__ x_in,
    const float* __restrict__ Wl, const float* __restrict__ bl,
    const float* __restrict__ Wr, const float* __restrict__ br,
    int use_h)
{
    const float* A = use_h ? d_h : x_in;
    int mat  = blockIdx.y >> 1;
    int col0 = (blockIdx.y & 1) * 64;
    const float* W    = mat ? Wr : Wl;
    const float* bias = mat ? br : bl;
    float* O          = mat ? d_xr : d_xl;
    int row0 = blockIdx.x * 64;

    __shared__ float As[64][APITCH];        // [row][k] within chunk
    __shared__ float Bs[8][4][16][2];       // [k2][j][tc][k parity]

    int tid = threadIdx.x;
    int tr = tid >> 4, tc = tid & 15;       // microtile coords
    int lr = tid >> 2, lq = tid & 3;        // load coords: row 0..63, quad 0..3

    unsigned long long acc[4][4] = {};

    const float* Arow = A + (size_t)(row0 + lr) * 128;
    bool arow_ok = (row0 + lr) < GN;
    const float* Wrow = W + (size_t)(col0 + lr) * 128;

    for (int kc = 0; kc < 128; kc += 16) {
        float4 av = arow_ok ? *(const float4*)(Arow + kc + lq * 4)
                            : make_float4(0.f, 0.f, 0.f, 0.f);
        *(float4*)&As[lr][lq * 4] = av;
        float4 wv = *(const float4*)(Wrow + kc + lq * 4);
        int c = lr;
        int jj = c & 3, tt = c >> 2;
        *(float2*)&Bs[2 * lq][jj][tt][0]     = make_float2(wv.x, wv.y);
        *(float2*)&Bs[2 * lq + 1][jj][tt][0] = make_float2(wv.z, wv.w);
        __syncthreads();

        #pragma unroll
        for (int k2 = 0; k2 < 8; k2++) {
            unsigned long long pa[4], pb[4];
            #pragma unroll
            for (int i = 0; i < 4; i++)
                pa[i] = *(const unsigned long long*)&As[tr * 4 + i][k2 * 2];
            #pragma unroll
            for (int j = 0; j < 4; j++)
                pb[j] = *(const unsigned long long*)&Bs[k2][j][tc][0];
            #pragma unroll
            for (int i = 0; i < 4; i++)
                #pragma unroll
                for (int j = 0; j < 4; j++)
                    ffma2(acc[i][j], pa[i], pb[j]);
        }
        __syncthreads();
    }

    #pragma unroll
    for (int i = 0; i < 4; i++) {
        int gr = row0 + tr * 4 + i;
        if (gr < GN) {
            int c = col0 + tc * 4;
            float4 o;
            o.x = lo32(acc[i][0]) + hi32(acc[i][0]) + bias[c + 0];
            o.y = lo32(acc[i][1]) + hi32(acc[i][1]) + bias[c + 1];
            o.z = lo32(acc[i][2]) + hi32(acc[i][2]) + bias[c + 2];
            o.w = lo32(acc[i][3]) + hi32(acc[i][3]) + bias[c + 3];
            *(float4*)&O[(size_t)gr * 128 + c] = o;
        }
    }
}

// ---------------- fused GATv2 softmax + aggregation (warp per dst row) ----
// lane l holds channels 4l..4l+3 (all in head l>>3). One LDG.128 per edge,
// 3-shuffle octet reduce, branchless lane-local online softmax.
__global__ void __launch_bounds__(256) gat_row_kernel(const float* __restrict__ att,
                                                      const float* __restrict__ bias)
{
    int row = blockIdx.x * 8 + (threadIdx.x >> 5);
    if (row >= GN) return;
    int lane = threadIdx.x & 31;

    float4 attv = ((const float4*)att)[lane];
    float4 xrv  = ((const float4*)d_xr)[(size_t)row * 32 + lane];

    int e0 = d_rowstart[row], e1 = d_rowstart[row + 1];

    float mx = -1e30f, dn = 0.f;
    float4 ac = make_float4(0.f, 0.f, 0.f, 0.f);

    const float4* XL = (const float4*)d_xl;
    int s = d_csrsrc[e0];
    float4 xv = XL[(size_t)s * 32 + lane];

    for (int j = e0; j < e1; j++) {
        int sn = (j + 1 < e1) ? d_csrsrc[j + 1] : 0;
        float4 xn = XL[(size_t)sn * 32 + lane];

        float v, lg;
        v = xv.x + xrv.x; v = v > 0.f ? v : 0.2f * v; lg = v * attv.x;
        v = xv.y + xrv.y; v = v > 0.f ? v : 0.2f * v; lg = fmaf(v, attv.y, lg);
        v = xv.z + xrv.z; v = v > 0.f ? v : 0.2f * v; lg = fmaf(v, attv.z, lg);
        v = xv.w + xrv.w; v = v > 0.f ? v : 0.2f * v; lg = fmaf(v, attv.w, lg);
        lg += __shfl_xor_sync(0xffffffffu, lg, 4);
        lg += __shfl_xor_sync(0xffffffffu, lg, 2);
        lg += __shfl_xor_sync(0xffffffffu, lg, 1);

        float nm = fmaxf(mx, lg);
        float a  = __expf(mx - nm);
        float w  = __expf(lg - nm);
        dn = dn * a + w;
        ac.x = fmaf(ac.x, a, w * xv.x);
        ac.y = fmaf(ac.y, a, w * xv.y);
        ac.z = fmaf(ac.z, a, w * xv.z);
        ac.w = fmaf(ac.w, a, w * xv.w);
        mx = nm;
        xv = xn;
    }

    float inv = 1.f / dn;
    float4 bv = ((const float4*)bias)[lane];
    float4 o;
    o.x = fmaxf(fmaf(ac.x, inv, bv.x), 0.f);
    o.y = fmaxf(fmaf(ac.y, inv, bv.y), 0.f);
    o.z = fmaxf(fmaf(ac.z, inv, bv.z), 0.f);
    o.w = fmaxf(fmaf(ac.w, inv, bv.w), 0.f);
    ((float4*)d_h)[(size_t)row * 32 + lane] = o;
}

// ---------------- pooling ----------------
__global__ void zero_pool_kernel() {
    int i = blockIdx.x * blockDim.x + threadIdx.x;
    if (i < GG * 128) d_pool[i] = 0.f;
    if (i < GG) d_cnt[i] = 0.f;
}

__global__ void count_kernel(const void* __restrict__ batch) {
    int i = blockIdx.x * blockDim.x + threadIdx.x;
    if (i >= GN) return;
    int g = edge_at(batch, i, d_is64);
    atomicAdd(&d_cnt[g], 1.f);
}

__global__ void pool_kernel(const void* __restrict__ batch) {
    const int CHUNK = 256;
    int n0 = blockIdx.x * CHUNK;
    int n1 = n0 + CHUNK; if (n1 > GN) n1 = GN;
    int col = threadIdx.x;
    int is64 = d_is64;
    int curg = -1;
    float acc = 0.f;
    for (int n = n0; n < n1; n++) {
        int g = edge_at(batch, n, is64);
        if (g != curg) {
            if (curg >= 0) atomicAdd(&d_pool[curg * 128 + col], acc);
            curg = g; acc = 0.f;
        }
        acc += d_h[n * 128 + col];
    }
    if (curg >= 0) atomicAdd(&d_pool[curg * 128 + col], acc);
}

// ---------------- classifier ----------------
__global__ void classifier_kernel(
    const float* __restrict__ Wc1, const float* __restrict__ bc1,
    const float* __restrict__ Wc2, const float* __restrict__ bc2,
    float* __restrict__ out)
{
    int g = threadIdx.x;
    if (g >= GG) return;
    float inv = 1.f / fmaxf(d_cnt[g], 1.f);
    float z[8];
    #pragma unroll
    for (int j = 0; j < 8; j++) {
        float s = 0.f;
        for (int k = 0; k < 128; k++)
            s += d_pool[g * 128 + k] * Wc1[j * 128 + k];
        s = s * inv + bc1[j];
        z[j] = fmaxf(s, 0.f);
    }
    float o = bc2[0];
    #pragma unroll
    for (int j = 0; j < 8; j++) o += z[j] * Wc2[j];
    out[g] = o;
}

// ---------------- launch ----------------
extern "C" void kernel_launch(void* const* d_in, const int* in_sizes, int n_in,
                              void* d_out, int out_size) {
    const float* x     = (const float*)d_in[0];
    const void*  ei    = d_in[1];
    const void*  batch = d_in[2];
    const float* Wl0 = (const float*)d_in[3];
    const float* bl0 = (const float*)d_in[4];
    const float* Wr0 = (const float*)d_in[5];
    const float* br0 = (const float*)d_in[6];
    const float* at0 = (const float*)d_in[7];
    const float* bi0 = (const float*)d_in[8];
    const float* Wl1 = (const float*)d_in[9];
    const float* bl1 = (const float*)d_in[10];
    const float* Wr1 = (const float*)d_in[11];
    const float* br1 = (const float*)d_in[12];
    const float* at1 = (const float*)d_in[13];
    const float* bi1 = (const float*)d_in[14];
    const float* Wc1 = (const float*)d_in[15];
    const float* bc1 = (const float*)d_in[16];
    const float* Wc2 = (const float*)d_in[17];
    const float* bc2 = (const float*)d_in[18];
    float* out = (float*)d_out;

    detect_kernel<<<1, 32>>>((const int*)ei);

    // CSR build (dst-sorted), reused by both layers
    zero_cnt_kernel<<<(GN + 255) / 256, 256>>>();
    hist_kernel<<<(EP + 255) / 256, 256>>>(ei);
    chunk_sum_kernel<<<NCH, 256>>>();
    tops_kernel<<<1, 32>>>();
    scan_apply_kernel<<<NCH, 512>>>();
    scatter_kernel<<<(EP + 255) / 256, 256>>>(ei);

    for (int layer = 0; layer < 2; layer++) {
        const float* Wl = layer ? Wl1 : Wl0;
        const float* bl = layer ? bl1 : bl0;
        const float* Wr = layer ? Wr1 : Wr0;
        const float* br = layer ? br1 : br0;
        const float* at = layer ? at1 : at0;
        const float* bi = layer ? bi1 : bi0;

        gemm_kernel<<<dim3((GN + 63) / 64, 4), 256>>>(x, Wl, bl, Wr, br, layer);
        gat_row_kernel<<<(GN + 7) / 8, 256>>>(at, bi);
    }

    zero_pool_kernel<<<(GG * 128 + 255) / 256, 256>>>();
    count_kernel<<<(GN + 255) / 256, 256>>>(batch);
    pool_kernel<<<(GN + 255) / 256, 128>>>(batch);
    classifier_kernel<<<1, 64>>>(Wc1, bc1, Wc2, bc2, out);
}

// round 5
// speedup vs baseline: 1.6258x; 1.0245x over previous
#include <cuda_runtime.h>

#define GN 50000
#define GE 800000
#define EP 850000   // GE + GN self-loops
#define GG 64
#define NCH 98      // ceil(GN/512)

// ---------------- scratch (device globals; no allocation) ----------------
__device__ __align__(16) float d_xl[GN * 128];
__device__ __align__(16) float d_xr[GN * 128];
__device__ __align__(16) float d_h[GN * 128];
__device__ int   d_rowcnt[GN];
__device__ int   d_rowstart[GN + 1];
__device__ int   d_rowfill[GN];
__device__ int   d_csrsrc[EP];
__device__ int   d_chunksum[NCH];
__device__ float d_pool[GG * 128];
__device__ float d_cnt[GG];
__device__ int   d_is64;

// ---------------- int32/int64 width detection ----------------
__global__ void detect_kernel(const int* __restrict__ ei32) {
    if (threadIdx.x == 0 && blockIdx.x == 0) {
        int any = 0;
        #pragma unroll
        for (int i = 1; i < 128; i += 2) any |= ei32[i];
        d_is64 = (any == 0) ? 1 : 0;
    }
}

__device__ __forceinline__ int edge_at(const void* ei, int idx, int is64) {
    return is64 ? (int)((const long long*)ei)[idx] : ((const int*)ei)[idx];
}

// ---------------- CSR build: hist -> scan -> scatter ----------------
__global__ void zero_cnt_kernel() {
    int i = blockIdx.x * blockDim.x + threadIdx.x;
    if (i < GN) d_rowcnt[i] = 0;
}

__global__ void hist_kernel(const void* __restrict__ ei) {
    int i = blockIdx.x * blockDim.x + threadIdx.x;
    if (i >= EP) return;
    int is64 = d_is64;
    int dd = (i < GE) ? edge_at(ei, GE + i, is64) : (i - GE);
    atomicAdd(&d_rowcnt[dd], 1);
}

__global__ void chunk_sum_kernel() {
    __shared__ int sh[256];
    int b = blockIdx.x, t = threadIdx.x;
    int base = b * 512;
    int v = 0;
    int i0 = base + t;       if (i0 < GN) v += d_rowcnt[i0];
    int i1 = base + 256 + t; if (i1 < GN) v += d_rowcnt[i1];
    sh[t] = v; __syncthreads();
    for (int off = 128; off; off >>= 1) {
        if (t < off) sh[t] += sh[t + off];
        __syncthreads();
    }
    if (t == 0) d_chunksum[b] = sh[0];
}

__global__ void tops_kernel() {
    if (threadIdx.x == 0) {
        int run = 0;
        for (int b = 0; b < NCH; b++) { int t = d_chunksum[b]; d_chunksum[b] = run; run += t; }
        d_rowstart[GN] = EP;
    }
}

__global__ void scan_apply_kernel() {
    __shared__ int sh[512];
    int b = blockIdx.x, t = threadIdx.x;
    int i = b * 512 + t;
    int v = (i < GN) ? d_rowcnt[i] : 0;
    sh[t] = v; __syncthreads();
    for (int off = 1; off < 512; off <<= 1) {
        int a = (t >= off) ? sh[t - off] : 0;
        __syncthreads();
        sh[t] += a;
        __syncthreads();
    }
    if (i < GN) {
        int excl = sh[t] - v + d_chunksum[b];
        d_rowstart[i] = excl;
        d_rowfill[i]  = excl;
    }
}

__global__ void scatter_kernel(const void* __restrict__ ei) {
    int i = blockIdx.x * blockDim.x + threadIdx.x;
    if (i >= EP) return;
    int is64 = d_is64;
    int ss, dd;
    if (i < GE) { ss = edge_at(ei, i, is64); dd = edge_at(ei, GE + i, is64); }
    else        { ss = i - GE; dd = ss; }
    int pos = atomicAdd(&d_rowfill[dd], 1);
    d_csrsrc[pos] = ss;
}

// ---------------- GEMM with packed f32x2 FFMA ----------------
__device__ __forceinline__ void ffma2(unsigned long long& d,
                                      unsigned long long a,
                                      unsigned long long b) {
    asm("fma.rn.f32x2 %0, %1, %2, %0;" : "+l"(d) : "l"(a), "l"(b));
}
__device__ __forceinline__ float lo32(unsigned long long v) {
    return __uint_as_float((unsigned)(v & 0xffffffffull));
}
__device__ __forceinline__ float hi32(unsigned long long v) {
    return __uint_as_float((unsigned)(v >> 32));
}

#define APITCH 20

__global__ void __launch_bounds__(256) gemm_kernel(
    const float* __restrict__ x_in,
    const float* __restrict__ Wl, const float* __restrict__ bl,
    const float* __restrict__ Wr, const float* __restrict__ br,
    int use_h)
{
    const float* A = use_h ? d_h : x_in;
    int mat  = blockIdx.y >> 1;
    int col0 = (blockIdx.y & 1) * 64;
    const float* W    = mat ? Wr : Wl;
    const float* bias = mat ? br : bl;
    float* O          = mat ? d_xr : d_xl;
    int row0 = blockIdx.x * 64;

    __shared__ float As[64][APITCH];        // [row][k] within chunk
    __shared__ float Bs[8][4][16][2];       // [k2][j][tc][k parity]

    int tid = threadIdx.x;
    int tr = tid >> 4, tc = tid & 15;
    int lr = tid >> 2, lq = tid & 3;

    unsigned long long acc[4][4] = {};

    const float* Arow = A + (size_t)(row0 + lr) * 128;
    bool arow_ok = (row0 + lr) < GN;
    const float* Wrow = W + (size_t)(col0 + lr) * 128;

    for (int kc = 0; kc < 128; kc += 16) {
        float4 av = arow_ok ? *(const float4*)(Arow + kc + lq * 4)
                            : make_float4(0.f, 0.f, 0.f, 0.f);
        *(float4*)&As[lr][lq * 4] = av;
        float4 wv = *(const float4*)(Wrow + kc + lq * 4);
        int c = lr;
        int jj = c & 3, tt = c >> 2;
        *(float2*)&Bs[2 * lq][jj][tt][0]     = make_float2(wv.x, wv.y);
        *(float2*)&Bs[2 * lq + 1][jj][tt][0] = make_float2(wv.z, wv.w);
        __syncthreads();

        #pragma unroll
        for (int k2 = 0; k2 < 8; k2++) {
            unsigned long long pa[4], pb[4];
            #pragma unroll
            for (int i = 0; i < 4; i++)
                pa[i] = *(const unsigned long long*)&As[tr * 4 + i][k2 * 2];
            #pragma unroll
            for (int j = 0; j < 4; j++)
                pb[j] = *(const unsigned long long*)&Bs[k2][j][tc][0];
            #pragma unroll
            for (int i = 0; i < 4; i++)
                #pragma unroll
                for (int j = 0; j < 4; j++)
                    ffma2(acc[i][j], pa[i], pb[j]);
        }
        __syncthreads();
    }

    #pragma unroll
    for (int i = 0; i < 4; i++) {
        int gr = row0 + tr * 4 + i;
        if (gr < GN) {
            int c = col0 + tc * 4;
            float4 o;
            o.x = lo32(acc[i][0]) + hi32(acc[i][0]) + bias[c + 0];
            o.y = lo32(acc[i][1]) + hi32(acc[i][1]) + bias[c + 1];
            o.z = lo32(acc[i][2]) + hi32(acc[i][2]) + bias[c + 2];
            o.w = lo32(acc[i][3]) + hi32(acc[i][3]) + bias[c + 3];
            *(float4*)&O[(size_t)gr * 128 + c] = o;
        }
    }
}

// ---------------- fused GATv2 softmax + aggregation (warp per dst row) ----
// Two edges in flight per iteration: independent logit/SHFL chains, pairwise
// softmax merge, then one running merge. Prefetch one pair ahead.
__device__ __forceinline__ float edge_logit(const float4& xv, const float4& xrv,
                                            const float4& attv) {
    float v, lg;
    v = xv.x + xrv.x; v = v > 0.f ? v : 0.2f * v; lg = v * attv.x;
    v = xv.y + xrv.y; v = v > 0.f ? v : 0.2f * v; lg = fmaf(v, attv.y, lg);
    v = xv.z + xrv.z; v = v > 0.f ? v : 0.2f * v; lg = fmaf(v, attv.z, lg);
    v = xv.w + xrv.w; v = v > 0.f ? v : 0.2f * v; lg = fmaf(v, attv.w, lg);
    return lg;
}

__global__ void __launch_bounds__(256) gat_row_kernel(const float* __restrict__ att,
                                                      const float* __restrict__ bias)
{
    int row = blockIdx.x * 8 + (threadIdx.x >> 5);
    if (row >= GN) return;
    int lane = threadIdx.x & 31;

    float4 attv = ((const float4*)att)[lane];
    float4 xrv  = ((const float4*)d_xr)[(size_t)row * 32 + lane];

    int e0 = d_rowstart[row], e1 = d_rowstart[row + 1];
    int cnt = e1 - e0;

    float mx = -1e30f, dn = 0.f;
    float4 ac = make_float4(0.f, 0.f, 0.f, 0.f);

    const float4* XL = (const float4*)d_xl;

    float4 xv0, xv1;
    if (cnt >= 2) {
        int s0 = d_csrsrc[e0], s1 = d_csrsrc[e0 + 1];
        xv0 = XL[(size_t)s0 * 32 + lane];
        xv1 = XL[(size_t)s1 * 32 + lane];
    }

    for (int j = e0; j + 1 < e1; j += 2) {
        int n0 = (j + 2 < e1) ? d_csrsrc[j + 2] : 0;
        int n1 = (j + 3 < e1) ? d_csrsrc[j + 3] : 0;
        float4 xn0 = XL[(size_t)n0 * 32 + lane];
        float4 xn1 = XL[(size_t)n1 * 32 + lane];

        float lg0 = edge_logit(xv0, xrv, attv);
        float lg1 = edge_logit(xv1, xrv, attv);
        lg0 += __shfl_xor_sync(0xffffffffu, lg0, 4);
        lg1 += __shfl_xor_sync(0xffffffffu, lg1, 4);
        lg0 += __shfl_xor_sync(0xffffffffu, lg0, 2);
        lg1 += __shfl_xor_sync(0xffffffffu, lg1, 2);
        lg0 += __shfl_xor_sync(0xffffffffu, lg0, 1);
        lg1 += __shfl_xor_sync(0xffffffffu, lg1, 1);

        // pair-local softmax combine
        float m  = fmaxf(lg0, lg1);
        float w0 = __expf(lg0 - m);
        float w1 = __expf(lg1 - m);
        float pd = w0 + w1;
        float4 pa;
        pa.x = fmaf(w1, xv1.x, w0 * xv0.x);
        pa.y = fmaf(w1, xv1.y, w0 * xv0.y);
        pa.z = fmaf(w1, xv1.z, w0 * xv0.z);
        pa.w = fmaf(w1, xv1.w, w0 * xv0.w);

        // merge into running state
        float nm = fmaxf(mx, m);
        float a  = __expf(mx - nm);
        float b  = __expf(m - nm);
        dn = fmaf(dn, a, pd * b);
        ac.x = fmaf(ac.x, a, pa.x * b);
        ac.y = fmaf(ac.y, a, pa.y * b);
        ac.z = fmaf(ac.z, a, pa.z * b);
        ac.w = fmaf(ac.w, a, pa.w * b);
        mx = nm;

        xv0 = xn0; xv1 = xn1;
    }

    if (cnt & 1) {
        int s = d_csrsrc[e1 - 1];
        float4 xv = XL[(size_t)s * 32 + lane];
        float lg = edge_logit(xv, xrv, attv);
        lg += __shfl_xor_sync(0xffffffffu, lg, 4);
        lg += __shfl_xor_sync(0xffffffffu, lg, 2);
        lg += __shfl_xor_sync(0xffffffffu, lg, 1);
        float nm = fmaxf(mx, lg);
        float a  = __expf(mx - nm);
        float w  = __expf(lg - nm);
        dn = fmaf(dn, a, w);
        ac.x = fmaf(ac.x, a, w * xv.x);
        ac.y = fmaf(ac.y, a, w * xv.y);
        ac.z = fmaf(ac.z, a, w * xv.z);
        ac.w = fmaf(ac.w, a, w * xv.w);
        mx = nm;
    }

    float inv = 1.f / dn;
    float4 bv = ((const float4*)bias)[lane];
    float4 o;
    o.x = fmaxf(fmaf(ac.x, inv, bv.x), 0.f);
    o.y = fmaxf(fmaf(ac.y, inv, bv.y), 0.f);
    o.z = fmaxf(fmaf(ac.z, inv, bv.z), 0.f);
    o.w = fmaxf(fmaf(ac.w, inv, bv.w), 0.f);
    ((float4*)d_h)[(size_t)row * 32 + lane] = o;
}

// ---------------- pooling ----------------
__global__ void zero_pool_kernel() {
    int i = blockIdx.x * blockDim.x + threadIdx.x;
    if (i < GG * 128) d_pool[i] = 0.f;
    if (i < GG) d_cnt[i] = 0.f;
}

__global__ void count_kernel(const void* __restrict__ batch) {
    int i = blockIdx.x * blockDim.x + threadIdx.x;
    if (i >= GN) return;
    int g = edge_at(batch, i, d_is64);
    atomicAdd(&d_cnt[g], 1.f);
}

__global__ void pool_kernel(const void* __restrict__ batch) {
    const int CHUNK = 256;
    int n0 = blockIdx.x * CHUNK;
    int n1 = n0 + CHUNK; if (n1 > GN) n1 = GN;
    int col = threadIdx.x;
    int is64 = d_is64;
    int curg = -1;
    float acc = 0.f;
    for (int n = n0; n < n1; n++) {
        int g = edge_at(batch, n, is64);
        if (g != curg) {
            if (curg >= 0) atomicAdd(&d_pool[curg * 128 + col], acc);
            curg = g; acc = 0.f;
        }
        acc += d_h[n * 128 + col];
    }
    if (curg >= 0) atomicAdd(&d_pool[curg * 128 + col], acc);
}

// ---------------- classifier ----------------
__global__ void classifier_kernel(
    const float* __restrict__ Wc1, const float* __restrict__ bc1,
    const float* __restrict__ Wc2, const float* __restrict__ bc2,
    float* __restrict__ out)
{
    int g = threadIdx.x;
    if (g >= GG) return;
    float inv = 1.f / fmaxf(d_cnt[g], 1.f);
    float z[8];
    #pragma unroll
    for (int j = 0; j < 8; j++) {
        float s = 0.f;
        for (int k = 0; k < 128; k++)
            s += d_pool[g * 128 + k] * Wc1[j * 128 + k];
        s = s * inv + bc1[j];
        z[j] = fmaxf(s, 0.f);
    }
    float o = bc2[0];
    #pragma unroll
    for (int j = 0; j < 8; j++) o += z[j] * Wc2[j];
    out[g] = o;
}

// ---------------- launch ----------------
extern "C" void kernel_launch(void* const* d_in, const int* in_sizes, int n_in,
                              void* d_out, int out_size) {
    const float* x     = (const float*)d_in[0];
    const void*  ei    = d_in[1];
    const void*  batch = d_in[2];
    const float* Wl0 = (const float*)d_in[3];
    const float* bl0 = (const float*)d_in[4];
    const float* Wr0 = (const float*)d_in[5];
    const float* br0 = (const float*)d_in[6];
    const float* at0 = (const float*)d_in[7];
    const float* bi0 = (const float*)d_in[8];
    const float* Wl1 = (const float*)d_in[9];
    const float* bl1 = (const float*)d_in[10];
    const float* Wr1 = (const float*)d_in[11];
    const float* br1 = (const float*)d_in[12];
    const float* at1 = (const float*)d_in[13];
    const float* bi1 = (const float*)d_in[14];
    const float* Wc1 = (const float*)d_in[15];
    const float* bc1 = (const float*)d_in[16];
    const float* Wc2 = (const float*)d_in[17];
    const float* bc2 = (const float*)d_in[18];
    float* out = (float*)d_out;

    // Launch order chosen so gemm_kernel (layer 0) is the 4th launch:
    // the ncu window (-s 5 -c 1) profiles launch #4, giving us f32x2 GEMM data.
    detect_kernel<<<1, 32>>>((const int*)ei);                 // 1
    zero_cnt_kernel<<<(GN + 255) / 256, 256>>>();             // 2
    hist_kernel<<<(EP + 255) / 256, 256>>>(ei);               // 3
    gemm_kernel<<<dim3((GN + 63) / 64, 4), 256>>>(x, Wl0, bl0, Wr0, br0, 0);  // 4 (profiled)
    chunk_sum_kernel<<<NCH, 256>>>();                         // 5
    tops_kernel<<<1, 32>>>();                                 // 6
    scan_apply_kernel<<<NCH, 512>>>();                        // 7
    scatter_kernel<<<(EP + 255) / 256, 256>>>(ei);            // 8

    gat_row_kernel<<<(GN + 7) / 8, 256>>>(at0, bi0);          // layer 0 aggregate
    gemm_kernel<<<dim3((GN + 63) / 64, 4), 256>>>(x, Wl1, bl1, Wr1, br1, 1);
    gat_row_kernel<<<(GN + 7) / 8, 256>>>(at1, bi1);          // layer 1 aggregate

    zero_pool_kernel<<<(GG * 128 + 255) / 256, 256>>>();
    count_kernel<<<(GN + 255) / 256, 256>>>(batch);
    pool_kernel<<<(GN + 255) / 256, 128>>>(batch);
    classifier_kernel<<<1, 64>>>(Wc1, bc1, Wc2, bc2, out);
}

// round 6
// speedup vs baseline: 1.6737x; 1.0295x over previous
#include <cuda_runtime.h>

#define GN 50000
#define GE 800000
#define EP 850000   // GE + GN self-loops
#define GG 64
#define NCH 98      // ceil(GN/512)

// ---------------- scratch (device globals; no allocation) ----------------
__device__ __align__(16) float d_xl[GN * 128];
__device__ __align__(16) float d_xr[GN * 128];
__device__ __align__(16) float d_h[GN * 128];
__device__ __align__(16) float d_elog[(size_t)EP * 4];
__device__ int   d_rowcnt[GN];
__device__ int   d_rowstart[GN + 1];
__device__ int   d_rowfill[GN];
__device__ int   d_csrsrc[EP];
__device__ int   d_chunksum[NCH];
__device__ float d_pool[GG * 128];
__device__ float d_cnt[GG];
__device__ int   d_is64;

// ---------------- int32/int64 width detection ----------------
__global__ void detect_kernel(const int* __restrict__ ei32) {
    if (threadIdx.x == 0 && blockIdx.x == 0) {
        int any = 0;
        #pragma unroll
        for (int i = 1; i < 128; i += 2) any |= ei32[i];
        d_is64 = (any == 0) ? 1 : 0;
    }
}

__device__ __forceinline__ int edge_at(const void* ei, int idx, int is64) {
    return is64 ? (int)((const long long*)ei)[idx] : ((const int*)ei)[idx];
}

// ---------------- CSR build: hist -> scan -> scatter ----------------
__global__ void zero_cnt_kernel() {
    int i = blockIdx.x * blockDim.x + threadIdx.x;
    if (i < GN) d_rowcnt[i] = 0;
}

__global__ void hist_kernel(const void* __restrict__ ei) {
    int i = blockIdx.x * blockDim.x + threadIdx.x;
    if (i >= EP) return;
    int is64 = d_is64;
    int dd = (i < GE) ? edge_at(ei, GE + i, is64) : (i - GE);
    atomicAdd(&d_rowcnt[dd], 1);
}

__global__ void chunk_sum_kernel() {
    __shared__ int sh[256];
    int b = blockIdx.x, t = threadIdx.x;
    int base = b * 512;
    int v = 0;
    int i0 = base + t;       if (i0 < GN) v += d_rowcnt[i0];
    int i1 = base + 256 + t; if (i1 < GN) v += d_rowcnt[i1];
    sh[t] = v; __syncthreads();
    for (int off = 128; off; off >>= 1) {
        if (t < off) sh[t] += sh[t + off];
        __syncthreads();
    }
    if (t == 0) d_chunksum[b] = sh[0];
}

__global__ void tops_kernel() {
    if (threadIdx.x == 0) {
        int run = 0;
        for (int b = 0; b < NCH; b++) { int t = d_chunksum[b]; d_chunksum[b] = run; run += t; }
        d_rowstart[GN] = EP;
    }
}

__global__ void scan_apply_kernel() {
    __shared__ int sh[512];
    int b = blockIdx.x, t = threadIdx.x;
    int i = b * 512 + t;
    int v = (i < GN) ? d_rowcnt[i] : 0;
    sh[t] = v; __syncthreads();
    for (int off = 1; off < 512; off <<= 1) {
        int a = (t >= off) ? sh[t - off] : 0;
        __syncthreads();
        sh[t] += a;
        __syncthreads();
    }
    if (i < GN) {
        int excl = sh[t] - v + d_chunksum[b];
        d_rowstart[i] = excl;
        d_rowfill[i]  = excl;
    }
}

__global__ void scatter_kernel(const void* __restrict__ ei) {
    int i = blockIdx.x * blockDim.x + threadIdx.x;
    if (i >= EP) return;
    int is64 = d_is64;
    int ss, dd;
    if (i < GE) { ss = edge_at(ei, i, is64); dd = edge_at(ei, GE + i, is64); }
    else        { ss = i - GE; dd = ss; }
    int pos = atomicAdd(&d_rowfill[dd], 1);
    d_csrsrc[pos] = ss;
}

// ---------------- GEMM (scalar FFMA, 64x64 tile, 4x4 microtile) ----------
__global__ void __launch_bounds__(256) gemm_kernel(
    const float* __restrict__ x_in,
    const float* __restrict__ Wl, const float* __restrict__ bl,
    const float* __restrict__ Wr, const float* __restrict__ br,
    int use_h)
{
    const float* A = use_h ? d_h : x_in;
    int mat  = blockIdx.y >> 1;
    int col0 = (blockIdx.y & 1) * 64;
    const float* W    = mat ? Wr : Wl;
    const float* bias = mat ? br : bl;
    float* O          = mat ? d_xr : d_xl;
    int row0 = blockIdx.x * 64;

    __shared__ float As[16][68];
    __shared__ float Bs[16][68];

    int tid = threadIdx.x;
    int tr = tid >> 4, tc = tid & 15;
    int lk = tid & 15;
    int lr = tid >> 4;

    float acc[4][4] = {};

    for (int kc = 0; kc < 128; kc += 16) {
        #pragma unroll
        for (int p = 0; p < 4; p++) {
            int r  = lr + p * 16;
            int gr = row0 + r;
            As[lk][r] = (gr < GN) ? A[(size_t)gr * 128 + kc + lk] : 0.f;
            Bs[lk][r] = W[(size_t)(col0 + r) * 128 + kc + lk];
        }
        __syncthreads();
        #pragma unroll
        for (int k = 0; k < 16; k++) {
            float4 a = *(const float4*)&As[k][tr * 4];
            float4 b = *(const float4*)&Bs[k][tc * 4];
            acc[0][0] += a.x * b.x; acc[0][1] += a.x * b.y; acc[0][2] += a.x * b.z; acc[0][3] += a.x * b.w;
            acc[1][0] += a.y * b.x; acc[1][1] += a.y * b.y; acc[1][2] += a.y * b.z; acc[1][3] += a.y * b.w;
            acc[2][0] += a.z * b.x; acc[2][1] += a.z * b.y; acc[2][2] += a.z * b.z; acc[2][3] += a.z * b.w;
            acc[3][0] += a.w * b.x; acc[3][1] += a.w * b.y; acc[3][2] += a.w * b.z; acc[3][3] += a.w * b.w;
        }
        __syncthreads();
    }

    #pragma unroll
    for (int i = 0; i < 4; i++) {
        int gr = row0 + tr * 4 + i;
        if (gr < GN) {
            int c = col0 + tc * 4;
            float4 o;
            o.x = acc[i][0] + bias[c + 0];
            o.y = acc[i][1] + bias[c + 1];
            o.z = acc[i][2] + bias[c + 2];
            o.w = acc[i][3] + bias[c + 3];
            *(float4*)&O[(size_t)gr * 128 + c] = o;
        }
    }
}

// ---------------- fused GATv2: two-phase, warp per dst row ----------------
// Phase 1: logits + octet SHFL reduce, store per-(edge,head) logit, fmax chain.
// Phase 2: reload xv + logit, independent exp, 2-stream accumulate. No SHFLs,
// no online rescaling -> no long serial chains.
__device__ __forceinline__ float edge_logit(const float4& xv, const float4& xrv,
                                            const float4& attv) {
    float v, lg;
    v = xv.x + xrv.x; v = v > 0.f ? v : 0.2f * v; lg = v * attv.x;
    v = xv.y + xrv.y; v = v > 0.f ? v : 0.2f * v; lg = fmaf(v, attv.y, lg);
    v = xv.z + xrv.z; v = v > 0.f ? v : 0.2f * v; lg = fmaf(v, attv.z, lg);
    v = xv.w + xrv.w; v = v > 0.f ? v : 0.2f * v; lg = fmaf(v, attv.w, lg);
    return lg;
}

__global__ void __launch_bounds__(256) gat_row_kernel(const float* __restrict__ att,
                                                      const float* __restrict__ bias)
{
    int row = blockIdx.x * 8 + (threadIdx.x >> 5);
    if (row >= GN) return;
    int lane = threadIdx.x & 31;
    int head = lane >> 3;
    bool octlead = (lane & 7) == 0;

    float4 attv = ((const float4*)att)[lane];
    float4 xrv  = ((const float4*)d_xr)[(size_t)row * 32 + lane];

    int e0 = d_rowstart[row], e1 = d_rowstart[row + 1];
    int cnt = e1 - e0;

    const float4* XL = (const float4*)d_xl;

    // ---- phase 1: logits + max ----
    float mxA = -1e30f, mxB = -1e30f;
    {
        float4 xv0, xv1;
        if (cnt >= 2) {
            int s0 = d_csrsrc[e0], s1 = d_csrsrc[e0 + 1];
            xv0 = XL[(size_t)s0 * 32 + lane];
            xv1 = XL[(size_t)s1 * 32 + lane];
        }
        for (int j = e0; j + 1 < e1; j += 2) {
            int n0 = (j + 2 < e1) ? d_csrsrc[j + 2] : 0;
            int n1 = (j + 3 < e1) ? d_csrsrc[j + 3] : 0;
            float4 xn0 = XL[(size_t)n0 * 32 + lane];
            float4 xn1 = XL[(size_t)n1 * 32 + lane];

            float lg0 = edge_logit(xv0, xrv, attv);
            float lg1 = edge_logit(xv1, xrv, attv);
            lg0 += __shfl_xor_sync(0xffffffffu, lg0, 4);
            lg1 += __shfl_xor_sync(0xffffffffu, lg1, 4);
            lg0 += __shfl_xor_sync(0xffffffffu, lg0, 2);
            lg1 += __shfl_xor_sync(0xffffffffu, lg1, 2);
            lg0 += __shfl_xor_sync(0xffffffffu, lg0, 1);
            lg1 += __shfl_xor_sync(0xffffffffu, lg1, 1);

            if (octlead) {
                d_elog[(size_t)j * 4 + head]       = lg0;
                d_elog[(size_t)(j + 1) * 4 + head] = lg1;
            }
            mxA = fmaxf(mxA, lg0);
            mxB = fmaxf(mxB, lg1);
            xv0 = xn0; xv1 = xn1;
        }
        if (cnt & 1) {
            int s = d_csrsrc[e1 - 1];
            float4 xv = XL[(size_t)s * 32 + lane];
            float lg = edge_logit(xv, xrv, attv);
            lg += __shfl_xor_sync(0xffffffffu, lg, 4);
            lg += __shfl_xor_sync(0xffffffffu, lg, 2);
            lg += __shfl_xor_sync(0xffffffffu, lg, 1);
            if (octlead) d_elog[(size_t)(e1 - 1) * 4 + head] = lg;
            mxA = fmaxf(mxA, lg);
        }
    }
    float mx = fmaxf(mxA, mxB);   // per-lane = per-head max (replicated in octet)
    __syncwarp();

    // ---- phase 2: exp + accumulate (two independent streams) ----
    float dnA = 0.f, dnB = 0.f;
    float4 acA = make_float4(0.f, 0.f, 0.f, 0.f);
    float4 acB = make_float4(0.f, 0.f, 0.f, 0.f);
    {
        float4 xv0, xv1; float l0, l1;
        if (cnt >= 2) {
            int s0 = d_csrsrc[e0], s1 = d_csrsrc[e0 + 1];
            xv0 = XL[(size_t)s0 * 32 + lane];
            xv1 = XL[(size_t)s1 * 32 + lane];
            l0 = d_elog[(size_t)e0 * 4 + head];
            l1 = d_elog[(size_t)(e0 + 1) * 4 + head];
        }
        for (int j = e0; j + 1 < e1; j += 2) {
            int n0 = (j + 2 < e1) ? d_csrsrc[j + 2] : 0;
            int n1 = (j + 3 < e1) ? d_csrsrc[j + 3] : 0;
            float4 xn0 = XL[(size_t)n0 * 32 + lane];
            float4 xn1 = XL[(size_t)n1 * 32 + lane];
            float ln0 = (j + 2 < e1) ? d_elog[(size_t)(j + 2) * 4 + head] : 0.f;
            float ln1 = (j + 3 < e1) ? d_elog[(size_t)(j + 3) * 4 + head] : 0.f;

            float w0 = __expf(l0 - mx);
            float w1 = __expf(l1 - mx);
            dnA += w0; dnB += w1;
            acA.x = fmaf(w0, xv0.x, acA.x); acB.x = fmaf(w1, xv1.x, acB.x);
            acA.y = fmaf(w0, xv0.y, acA.y); acB.y = fmaf(w1, xv1.y, acB.y);
            acA.z = fmaf(w0, xv0.z, acA.z); acB.z = fmaf(w1, xv1.z, acB.z);
            acA.w = fmaf(w0, xv0.w, acA.w); acB.w = fmaf(w1, xv1.w, acB.w);

            xv0 = xn0; xv1 = xn1; l0 = ln0; l1 = ln1;
        }
        if (cnt & 1) {
            int s = d_csrsrc[e1 - 1];
            float4 xv = XL[(size_t)s * 32 + lane];
            float lg = d_elog[(size_t)(e1 - 1) * 4 + head];
            float w = __expf(lg - mx);
            dnA += w;
            acA.x = fmaf(w, xv.x, acA.x);
            acA.y = fmaf(w, xv.y, acA.y);
            acA.z = fmaf(w, xv.z, acA.z);
            acA.w = fmaf(w, xv.w, acA.w);
        }
    }

    float inv = 1.f / (dnA + dnB);
    float4 bv = ((const float4*)bias)[lane];
    float4 o;
    o.x = fmaxf(fmaf(acA.x + acB.x, inv, bv.x), 0.f);
    o.y = fmaxf(fmaf(acA.y + acB.y, inv, bv.y), 0.f);
    o.z = fmaxf(fmaf(acA.z + acB.z, inv, bv.z), 0.f);
    o.w = fmaxf(fmaf(acA.w + acB.w, inv, bv.w), 0.f);
    ((float4*)d_h)[(size_t)row * 32 + lane] = o;
}

// ---------------- pooling ----------------
__global__ void zero_pool_kernel() {
    int i = blockIdx.x * blockDim.x + threadIdx.x;
    if (i < GG * 128) d_pool[i] = 0.f;
    if (i < GG) d_cnt[i] = 0.f;
}

__global__ void count_kernel(const void* __restrict__ batch) {
    int i = blockIdx.x * blockDim.x + threadIdx.x;
    if (i >= GN) return;
    int g = edge_at(batch, i, d_is64);
    atomicAdd(&d_cnt[g], 1.f);
}

__global__ void pool_kernel(const void* __restrict__ batch) {
    const int CHUNK = 256;
    int n0 = blockIdx.x * CHUNK;
    int n1 = n0 + CHUNK; if (n1 > GN) n1 = GN;
    int col = threadIdx.x;
    int is64 = d_is64;
    int curg = -1;
    float acc = 0.f;
    for (int n = n0; n < n1; n++) {
        int g = edge_at(batch, n, is64);
        if (g != curg) {
            if (curg >= 0) atomicAdd(&d_pool[curg * 128 + col], acc);
            curg = g; acc = 0.f;
        }
        acc += d_h[(size_t)n * 128 + col];
    }
    if (curg >= 0) atomicAdd(&d_pool[curg * 128 + col], acc);
}

// ---------------- classifier ----------------
__global__ void classifier_kernel(
    const float* __restrict__ Wc1, const float* __restrict__ bc1,
    const float* __restrict__ Wc2, const float* __restrict__ bc2,
    float* __restrict__ out)
{
    int g = threadIdx.x;
    if (g >= GG) return;
    float inv = 1.f / fmaxf(d_cnt[g], 1.f);
    float z[8];
    #pragma unroll
    for (int j = 0; j < 8; j++) {
        float s = 0.f;
        for (int k = 0; k < 128; k++)
            s += d_pool[g * 128 + k] * Wc1[j * 128 + k];
        s = s * inv + bc1[j];
        z[j] = fmaxf(s, 0.f);
    }
    float o = bc2[0];
    #pragma unroll
    for (int j = 0; j < 8; j++) o += z[j] * Wc2[j];
    out[g] = o;
}

// ---------------- launch ----------------
extern "C" void kernel_launch(void* const* d_in, const int* in_sizes, int n_in,
                              void* d_out, int out_size) {
    const float* x     = (const float*)d_in[0];
    const void*  ei    = d_in[1];
    const void*  batch = d_in[2];
    const float* Wl0 = (const float*)d_in[3];
    const float* bl0 = (const float*)d_in[4];
    const float* Wr0 = (const float*)d_in[5];
    const float* br0 = (const float*)d_in[6];
    const float* at0 = (const float*)d_in[7];
    const float* bi0 = (const float*)d_in[8];
    const float* Wl1 = (const float*)d_in[9];
    const float* bl1 = (const float*)d_in[10];
    const float* Wr1 = (const float*)d_in[11];
    const float* br1 = (const float*)d_in[12];
    const float* at1 = (const float*)d_in[13];
    const float* bi1 = (const float*)d_in[14];
    const float* Wc1 = (const float*)d_in[15];
    const float* bc1 = (const float*)d_in[16];
    const float* Wc2 = (const float*)d_in[17];
    const float* bc2 = (const float*)d_in[18];
    float* out = (float*)d_out;

    // gat_row (layer 0) placed so a later profiling round can window it;
    // gemm stays 4th launch to confirm the scalar revert timing.
    detect_kernel<<<1, 32>>>((const int*)ei);                 // 1
    zero_cnt_kernel<<<(GN + 255) / 256, 256>>>();             // 2
    hist_kernel<<<(EP + 255) / 256, 256>>>(ei);               // 3
    gemm_kernel<<<dim3((GN + 63) / 64, 4), 256>>>(x, Wl0, bl0, Wr0, br0, 0);  // 4 (profiled)
    chunk_sum_kernel<<<NCH, 256>>>();                         // 5
    tops_kernel<<<1, 32>>>();                                 // 6
    scan_apply_kernel<<<NCH, 512>>>();                        // 7
    scatter_kernel<<<(EP + 255) / 256, 256>>>(ei);            // 8

    gat_row_kernel<<<(GN + 7) / 8, 256>>>(at0, bi0);
    gemm_kernel<<<dim3((GN + 63) / 64, 4), 256>>>(x, Wl1, bl1, Wr1, br1, 1);
    gat_row_kernel<<<(GN + 7) / 8, 256>>>(at1, bi1);

    zero_pool_kernel<<<(GG * 128 + 255) / 256, 256>>>();
    count_kernel<<<(GN + 255) / 256, 256>>>(batch);
    pool_kernel<<<(GN + 255) / 256, 128>>>(batch);
    classifier_kernel<<<1, 64>>>(Wc1, bc1, Wc2, bc2, out);
}

// round 8
// speedup vs baseline: 2.0624x; 1.2323x over previous
#include <cuda_runtime.h>

#define GN 50000
#define GE 800000
#define EP 850000   // GE + GN self-loops
#define GG 64
#define NCH 98      // ceil(GN/512)

// ---------------- scratch (device globals; no allocation) ----------------
__device__ __align__(16) float d_xl[GN * 128];
__device__ __align__(16) float d_xr[GN * 128];
__device__ __align__(16) float d_h[GN * 128];
__device__ int   d_rowcnt[GN];
__device__ int   d_rowstart[GN + 1];
__device__ int   d_rowfill[GN];
__device__ int   d_csrsrc[EP];
__device__ int   d_chunksum[NCH];
__device__ float d_pool[GG * 128];
__device__ float d_cnt[GG];
__device__ int   d_is64;

// ---------------- int32/int64 width detection ----------------
__global__ void detect_kernel(const int* __restrict__ ei32) {
    if (threadIdx.x == 0 && blockIdx.x == 0) {
        int any = 0;
        #pragma unroll
        for (int i = 1; i < 128; i += 2) any |= ei32[i];
        d_is64 = (any == 0) ? 1 : 0;
    }
}

__device__ __forceinline__ int edge_at(const void* ei, int idx, int is64) {
    return is64 ? (int)((const long long*)ei)[idx] : ((const int*)ei)[idx];
}

// ---------------- CSR build: hist -> scan -> scatter ----------------
__global__ void zero_cnt_kernel() {
    int i = blockIdx.x * blockDim.x + threadIdx.x;
    if (i < GN) d_rowcnt[i] = 0;
}

__global__ void hist_kernel(const void* __restrict__ ei) {
    int i = blockIdx.x * blockDim.x + threadIdx.x;
    if (i >= EP) return;
    int is64 = d_is64;
    int dd = (i < GE) ? edge_at(ei, GE + i, is64) : (i - GE);
    atomicAdd(&d_rowcnt[dd], 1);
}

__global__ void chunk_sum_kernel() {
    __shared__ int sh[256];
    int b = blockIdx.x, t = threadIdx.x;
    int base = b * 512;
    int v = 0;
    int i0 = base + t;       if (i0 < GN) v += d_rowcnt[i0];
    int i1 = base + 256 + t; if (i1 < GN) v += d_rowcnt[i1];
    sh[t] = v; __syncthreads();
    for (int off = 128; off; off >>= 1) {
        if (t < off) sh[t] += sh[t + off];
        __syncthreads();
    }
    if (t == 0) d_chunksum[b] = sh[0];
}

__global__ void tops_kernel() {
    if (threadIdx.x == 0) {
        int run = 0;
        for (int b = 0; b < NCH; b++) { int t = d_chunksum[b]; d_chunksum[b] = run; run += t; }
        d_rowstart[GN] = EP;
    }
}

__global__ void scan_apply_kernel() {
    __shared__ int sh[512];
    int b = blockIdx.x, t = threadIdx.x;
    int i = b * 512 + t;
    int v = (i < GN) ? d_rowcnt[i] : 0;
    sh[t] = v; __syncthreads();
    for (int off = 1; off < 512; off <<= 1) {
        int a = (t >= off) ? sh[t - off] : 0;
        __syncthreads();
        sh[t] += a;
        __syncthreads();
    }
    if (i < GN) {
        int excl = sh[t] - v + d_chunksum[b];
        d_rowstart[i] = excl;
        d_rowfill[i]  = excl;
    }
}

__global__ void scatter_kernel(const void* __restrict__ ei) {
    int i = blockIdx.x * blockDim.x + threadIdx.x;
    if (i >= EP) return;
    int is64 = d_is64;
    int ss, dd;
    if (i < GE) { ss = edge_at(ei, i, is64); dd = edge_at(ei, GE + i, is64); }
    else        { ss = i - GE; dd = ss; }
    int pos = atomicAdd(&d_rowfill[dd], 1);
    d_csrsrc[pos] = ss;
}

// ---------------- tf32x3 tensor-core GEMM ----------------
// O = A @ W^T + bias, A:[GN,128], W:[128,128]. Block tile 128x128, 8 warps
// of 32x64. mma.m16n8k8 tf32 with hi/lo error compensation (3 mma / tile).
__device__ __forceinline__ void tf32_split(float x, float& hi, float& lo) {
    unsigned u;
    asm("cvt.rna.tf32.f32 %0, %1;" : "=r"(u) : "f"(x));
    hi = __uint_as_float(u);
    float r = x - hi;
    unsigned v;
    asm("cvt.rna.tf32.f32 %0, %1;" : "=r"(v) : "f"(r));
    lo = __uint_as_float(v);
}

__device__ __forceinline__ void mma_tf32(float* c,
                                         float a0, float a1, float a2, float a3,
                                         float b0, float b1) {
    asm("mma.sync.aligned.m16n8k8.row.col.f32.tf32.tf32.f32 "
        "{%0,%1,%2,%3}, {%4,%5,%6,%7}, {%8,%9}, {%0,%1,%2,%3};"
        : "+f"(c[0]), "+f"(c[1]), "+f"(c[2]), "+f"(c[3])
        : "r"(__float_as_uint(a0)), "r"(__float_as_uint(a1)),
          "r"(__float_as_uint(a2)), "r"(__float_as_uint(a3)),
          "r"(__float_as_uint(b0)), "r"(__float_as_uint(b1)));
}

#define SP 136   // smem pitch (floats): conflict-free fragment LDS

__global__ void __launch_bounds__(256) gemm_kernel(
    const float* __restrict__ x_in,
    const float* __restrict__ Wl, const float* __restrict__ bl,
    const float* __restrict__ Wr, const float* __restrict__ br,
    int use_h)
{
    const float* A = use_h ? d_h : x_in;
    int mat = blockIdx.y;
    const float* W    = mat ? Wr : Wl;
    const float* bias = mat ? br : bl;
    float* O          = mat ? d_xr : d_xl;
    int row0 = blockIdx.x * 128;

    __shared__ float As_hi[8 * SP];
    __shared__ float As_lo[8 * SP];
    __shared__ float Bs_hi[8 * SP];
    __shared__ float Bs_lo[8 * SP];

    int tid  = threadIdx.x;
    int w    = tid >> 5;
    int lane = tid & 31;
    int g    = lane >> 2;      // 0..7
    int t4   = lane & 3;       // 0..3
    int rw   = (w & 3) * 32;   // warp row base within tile
    int cw   = (w >> 2) * 64;  // warp col base

    int lrow = tid >> 1;       // 0..127 (row for A load, col for W load)
    int lq   = tid & 1;        // k-quad 0/1

    bool okA = (row0 + lrow) < GN;
    const float* Aptr = A + (size_t)(row0 + lrow) * 128 + lq * 4;
    const float* Wptr = W + (size_t)lrow * 128 + lq * 4;

    float acc[2][8][4];
    #pragma unroll
    for (int m = 0; m < 2; m++)
        #pragma unroll
        for (int n = 0; n < 8; n++)
            #pragma unroll
            for (int q = 0; q < 4; q++) acc[m][n][q] = 0.f;

    float4 av = okA ? *(const float4*)Aptr : make_float4(0.f, 0.f, 0.f, 0.f);
    float4 wv = *(const float4*)Wptr;

    for (int kc = 0; kc < 16; kc++) {
        float ah[4], al[4], wh[4], wl[4];
        tf32_split(av.x, ah[0], al[0]); tf32_split(av.y, ah[1], al[1]);
        tf32_split(av.z, ah[2], al[2]); tf32_split(av.w, ah[3], al[3]);
        tf32_split(wv.x, wh[0], wl[0]); tf32_split(wv.y, wh[1], wl[1]);
        tf32_split(wv.z, wh[2], wl[2]); tf32_split(wv.w, wh[3], wl[3]);

        __syncthreads();
        #pragma unroll
        for (int m = 0; m < 4; m++) {
            int k = lq * 4 + m;
            As_hi[k * SP + lrow] = ah[m];
            As_lo[k * SP + lrow] = al[m];
            Bs_hi[k * SP + lrow] = wh[m];
            Bs_lo[k * SP + lrow] = wl[m];
        }
        __syncthreads();

        if (kc < 15) {
            av = okA ? *(const float4*)(Aptr + (kc + 1) * 8)
                     : make_float4(0.f, 0.f, 0.f, 0.f);
            wv = *(const float4*)(Wptr + (kc + 1) * 8);
        }

        // A fragments for both m-tiles (hi & lo)
        float Ah[2][4], Al[2][4];
        #pragma unroll
        for (int m = 0; m < 2; m++) {
            int rb = rw + m * 16;
            Ah[m][0] = As_hi[t4 * SP + rb + g];
            Ah[m][1] = As_hi[t4 * SP + rb + g + 8];
            Ah[m][2] = As_hi[(t4 + 4) * SP + rb + g];
            Ah[m][3] = As_hi[(t4 + 4) * SP + rb + g + 8];
            Al[m][0] = As_lo[t4 * SP + rb + g];
            Al[m][1] = As_lo[t4 * SP + rb + g + 8];
            Al[m][2] = As_lo[(t4 + 4) * SP + rb + g];
            Al[m][3] = As_lo[(t4 + 4) * SP + rb + g + 8];
        }

        #pragma unroll
        for (int n = 0; n < 8; n++) {
            int cb = cw + n * 8;
            float bh0 = Bs_hi[t4 * SP + cb + g];
            float bh1 = Bs_hi[(t4 + 4) * SP + cb + g];
            float bl0 = Bs_lo[t4 * SP + cb + g];
            float bl1 = Bs_lo[(t4 + 4) * SP + cb + g];
            #pragma unroll
            for (int m = 0; m < 2; m++) {
                mma_tf32(acc[m][n], Ah[m][0], Ah[m][1], Ah[m][2], Ah[m][3], bh0, bh1);
                mma_tf32(acc[m][n], Ah[m][0], Ah[m][1], Ah[m][2], Ah[m][3], bl0, bl1);
                mma_tf32(acc[m][n], Al[m][0], Al[m][1], Al[m][2], Al[m][3], bh0, bh1);
            }
        }
    }

    // epilogue: D rows (row0+rw+m*16+g, +8), cols cw+n*8+t4*2 (+1)
    #pragma unroll
    for (int m = 0; m < 2; m++) {
        int r0 = row0 + rw + m * 16 + g;
        int r1 = r0 + 8;
        #pragma unroll
        for (int n = 0; n < 8; n++) {
            int cb = cw + n * 8 + t4 * 2;
            float b0 = bias[cb], b1 = bias[cb + 1];
            if (r0 < GN) {
                float2 v0 = make_float2(acc[m][n][0] + b0, acc[m][n][1] + b1);
                *(float2*)&O[(size_t)r0 * 128 + cb] = v0;
            }
            if (r1 < GN) {
                float2 v1 = make_float2(acc[m][n][2] + b0, acc[m][n][3] + b1);
                *(float2*)&O[(size_t)r1 * 128 + cb] = v1;
            }
        }
    }
}

// ---------------- fused GATv2 (pairwise single-pass, warp per row) -------
__device__ __forceinline__ float edge_logit(const float4& xv, const float4& xrv,
                                            const float4& attv) {
    float v, lg;
    v = xv.x + xrv.x; v = v > 0.f ? v : 0.2f * v; lg = v * attv.x;
    v = xv.y + xrv.y; v = v > 0.f ? v : 0.2f * v; lg = fmaf(v, attv.y, lg);
    v = xv.z + xrv.z; v = v > 0.f ? v : 0.2f * v; lg = fmaf(v, attv.z, lg);
    v = xv.w + xrv.w; v = v > 0.f ? v : 0.2f * v; lg = fmaf(v, attv.w, lg);
    return lg;
}

__global__ void __launch_bounds__(256) gat_row_kernel(const float* __restrict__ att,
                                                      const float* __restrict__ bias)
{
    int row = blockIdx.x * 8 + (threadIdx.x >> 5);
    if (row >= GN) return;
    int lane = threadIdx.x & 31;

    float4 attv = ((const float4*)att)[lane];
    float4 xrv  = ((const float4*)d_xr)[(size_t)row * 32 + lane];

    int e0 = d_rowstart[row], e1 = d_rowstart[row + 1];
    int cnt = e1 - e0;

    float mx = -1e30f, dn = 0.f;
    float4 ac = make_float4(0.f, 0.f, 0.f, 0.f);

    const float4* XL = (const float4*)d_xl;

    float4 xv0, xv1;
    if (cnt >= 2) {
        int s0 = d_csrsrc[e0], s1 = d_csrsrc[e0 + 1];
        xv0 = XL[(size_t)s0 * 32 + lane];
        xv1 = XL[(size_t)s1 * 32 + lane];
    }

    for (int j = e0; j + 1 < e1; j += 2) {
        int n0 = (j + 2 < e1) ? d_csrsrc[j + 2] : 0;
        int n1 = (j + 3 < e1) ? d_csrsrc[j + 3] : 0;
        float4 xn0 = XL[(size_t)n0 * 32 + lane];
        float4 xn1 = XL[(size_t)n1 * 32 + lane];

        float lg0 = edge_logit(xv0, xrv, attv);
        float lg1 = edge_logit(xv1, xrv, attv);
        lg0 += __shfl_xor_sync(0xffffffffu, lg0, 4);
        lg1 += __shfl_xor_sync(0xffffffffu, lg1, 4);
        lg0 += __shfl_xor_sync(0xffffffffu, lg0, 2);
        lg1 += __shfl_xor_sync(0xffffffffu, lg1, 2);
        lg0 += __shfl_xor_sync(0xffffffffu, lg0, 1);
        lg1 += __shfl_xor_sync(0xffffffffu, lg1, 1);

        float m  = fmaxf(lg0, lg1);
        float w0 = __expf(lg0 - m);
        float w1 = __expf(lg1 - m);
        float pd = w0 + w1;
        float4 pa;
        pa.x = fmaf(w1, xv1.x, w0 * xv0.x);
        pa.y = fmaf(w1, xv1.y, w0 * xv0.y);
        pa.z = fmaf(w1, xv1.z, w0 * xv0.z);
        pa.w = fmaf(w1, xv1.w, w0 * xv0.w);

        float nm = fmaxf(mx, m);
        float a  = __expf(mx - nm);
        float b  = __expf(m - nm);
        dn = fmaf(dn, a, pd * b);
        ac.x = fmaf(ac.x, a, pa.x * b);
        ac.y = fmaf(ac.y, a, pa.y * b);
        ac.z = fmaf(ac.z, a, pa.z * b);
        ac.w = fmaf(ac.w, a, pa.w * b);
        mx = nm;

        xv0 = xn0; xv1 = xn1;
    }

    if (cnt & 1) {
        int s = d_csrsrc[e1 - 1];
        float4 xv = XL[(size_t)s * 32 + lane];
        float lg = edge_logit(xv, xrv, attv);
        lg += __shfl_xor_sync(0xffffffffu, lg, 4);
        lg += __shfl_xor_sync(0xffffffffu, lg, 2);
        lg += __shfl_xor_sync(0xffffffffu, lg, 1);
        float nm = fmaxf(mx, lg);
        float a  = __expf(mx - nm);
        float w  = __expf(lg - nm);
        dn = fmaf(dn, a, w);
        ac.x = fmaf(ac.x, a, w * xv.x);
        ac.y = fmaf(ac.y, a, w * xv.y);
        ac.z = fmaf(ac.z, a, w * xv.z);
        ac.w = fmaf(ac.w, a, w * xv.w);
        mx = nm;
    }

    float inv = 1.f / dn;
    float4 bv = ((const float4*)bias)[lane];
    float4 o;
    o.x = fmaxf(fmaf(ac.x, inv, bv.x), 0.f);
    o.y = fmaxf(fmaf(ac.y, inv, bv.y), 0.f);
    o.z = fmaxf(fmaf(ac.z, inv, bv.z), 0.f);
    o.w = fmaxf(fmaf(ac.w, inv, bv.w), 0.f);
    ((float4*)d_h)[(size_t)row * 32 + lane] = o;
}

// ---------------- pooling ----------------
__global__ void zero_pool_kernel() {
    int i = blockIdx.x * blockDim.x + threadIdx.x;
    if (i < GG * 128) d_pool[i] = 0.f;
    if (i < GG) d_cnt[i] = 0.f;
}

__global__ void count_kernel(const void* __restrict__ batch) {
    int i = blockIdx.x * blockDim.x + threadIdx.x;
    if (i >= GN) return;
    int g = edge_at(batch, i, d_is64);
    atomicAdd(&d_cnt[g], 1.f);
}

__global__ void pool_kernel(const void* __restrict__ batch) {
    const int CHUNK = 256;
    int n0 = blockIdx.x * CHUNK;
    int n1 = n0 + CHUNK; if (n1 > GN) n1 = GN;
    int col = threadIdx.x;
    int is64 = d_is64;
    int curg = -1;
    float acc = 0.f;
    for (int n = n0; n < n1; n++) {
        int g = edge_at(batch, n, is64);
        if (g != curg) {
            if (curg >= 0) atomicAdd(&d_pool[curg * 128 + col], acc);
            curg = g; acc = 0.f;
        }
        acc += d_h[(size_t)n * 128 + col];
    }
    if (curg >= 0) atomicAdd(&d_pool[curg * 128 + col], acc);
}

// ---------------- classifier ----------------
__global__ void classifier_kernel(
    const float* __restrict__ Wc1, const float* __restrict__ bc1,
    const float* __restrict__ Wc2, const float* __restrict__ bc2,
    float* __restrict__ out)
{
    int g = threadIdx.x;
    if (g >= GG) return;
    float inv = 1.f / fmaxf(d_cnt[g], 1.f);
    float z[8];
    #pragma unroll
    for (int j = 0; j < 8; j++) {
        float s = 0.f;
        for (int k = 0; k < 128; k++)
            s += d_pool[g * 128 + k] * Wc1[j * 128 + k];
        s = s * inv + bc1[j];
        z[j] = fmaxf(s, 0.f);
    }
    float o = bc2[0];
    #pragma unroll
    for (int j = 0; j < 8; j++) o += z[j] * Wc2[j];
    out[g] = o;
}

// ---------------- launch ----------------
extern "C" void kernel_launch(void* const* d_in, const int* in_sizes, int n_in,
                              void* d_out, int out_size) {
    const float* x     = (const float*)d_in[0];
    const void*  ei    = d_in[1];
    const void*  batch = d_in[2];
    const float* Wl0 = (const float*)d_in[3];
    const float* bl0 = (const float*)d_in[4];
    const float* Wr0 = (const float*)d_in[5];
    const float* br0 = (const float*)d_in[6];
    const float* at0 = (const float*)d_in[7];
    const float* bi0 = (const float*)d_in[8];
    const float* Wl1 = (const float*)d_in[9];
    const float* bl1 = (const float*)d_in[10];
    const float* Wr1 = (const float*)d_in[11];
    const float* br1 = (const float*)d_in[12];
    const float* at1 = (const float*)d_in[13];
    const float* bi1 = (const float*)d_in[14];
    const float* Wc1 = (const float*)d_in[15];
    const float* bc1 = (const float*)d_in[16];
    const float* Wc2 = (const float*)d_in[17];
    const float* bc2 = (const float*)d_in[18];
    float* out = (float*)d_out;

    const dim3 GEMM_GRID((GN + 127) / 128, 2);

    // gemm is the 4th launch -> profiled by the ncu window (-s 5 -c 1).
    detect_kernel<<<1, 32>>>((const int*)ei);                 // 1
    zero_cnt_kernel<<<(GN + 255) / 256, 256>>>();             // 2
    hist_kernel<<<(EP + 255) / 256, 256>>>(ei);               // 3
    gemm_kernel<<<GEMM_GRID, 256>>>(x, Wl0, bl0, Wr0, br0, 0);// 4 (profiled)
    chunk_sum_kernel<<<NCH, 256>>>();                         // 5
    tops_kernel<<<1, 32>>>();                                 // 6
    scan_apply_kernel<<<NCH, 512>>>();                        // 7
    scatter_kernel<<<(EP + 255) / 256, 256>>>(ei);            // 8

    gat_row_kernel<<<(GN + 7) / 8, 256>>>(at0, bi0);
    gemm_kernel<<<GEMM_GRID, 256>>>(x, Wl1, bl1, Wr1, br1, 1);
    gat_row_kernel<<<(GN + 7) / 8, 256>>>(at1, bi1);

    zero_pool_kernel<<<(GG * 128 + 255) / 256, 256>>>();
    count_kernel<<<(GN + 255) / 256, 256>>>(batch);
    pool_kernel<<<(GN + 255) / 256, 128>>>(batch);
    classifier_kernel<<<1, 64>>>(Wc1, bc1, Wc2, bc2, out);
}

// round 9
// speedup vs baseline: 2.0774x; 1.0073x over previous
#include <cuda_runtime.h>

#define GN 50000
#define GE 800000
#define EP 850000   // GE + GN self-loops
#define GG 64
#define NCH 98      // ceil(GN/512)

// ---------------- scratch (device globals; no allocation) ----------------
__device__ __align__(16) float d_xl[GN * 128];
__device__ __align__(16) float d_xr[GN * 128];
__device__ __align__(16) float d_h[GN * 128];
__device__ int   d_rowcnt[GN];
__device__ int   d_rowstart[GN + 1];
__device__ int   d_rowfill[GN];
__device__ int   d_csrsrc[EP];
__device__ int   d_chunksum[NCH];
__device__ float d_pool[GG * 128];
__device__ float d_cnt[GG];
__device__ int   d_is64;

// ---------------- int32/int64 width detection ----------------
__global__ void detect_kernel(const int* __restrict__ ei32) {
    if (threadIdx.x == 0 && blockIdx.x == 0) {
        int any = 0;
        #pragma unroll
        for (int i = 1; i < 128; i += 2) any |= ei32[i];
        d_is64 = (any == 0) ? 1 : 0;
    }
}

__device__ __forceinline__ int edge_at(const void* ei, int idx, int is64) {
    return is64 ? (int)((const long long*)ei)[idx] : ((const int*)ei)[idx];
}

// ---------------- CSR build: hist -> scan -> scatter ----------------
__global__ void zero_cnt_kernel() {
    int i = blockIdx.x * blockDim.x + threadIdx.x;
    if (i < GN) d_rowcnt[i] = 0;
}

__global__ void hist_kernel(const void* __restrict__ ei) {
    int i = blockIdx.x * blockDim.x + threadIdx.x;
    if (i >= EP) return;
    int is64 = d_is64;
    int dd = (i < GE) ? edge_at(ei, GE + i, is64) : (i - GE);
    atomicAdd(&d_rowcnt[dd], 1);
}

__global__ void chunk_sum_kernel() {
    __shared__ int sh[256];
    int b = blockIdx.x, t = threadIdx.x;
    int base = b * 512;
    int v = 0;
    int i0 = base + t;       if (i0 < GN) v += d_rowcnt[i0];
    int i1 = base + 256 + t; if (i1 < GN) v += d_rowcnt[i1];
    sh[t] = v; __syncthreads();
    for (int off = 128; off; off >>= 1) {
        if (t < off) sh[t] += sh[t + off];
        __syncthreads();
    }
    if (t == 0) d_chunksum[b] = sh[0];
}

__global__ void tops_kernel() {
    if (threadIdx.x == 0) {
        int run = 0;
        for (int b = 0; b < NCH; b++) { int t = d_chunksum[b]; d_chunksum[b] = run; run += t; }
        d_rowstart[GN] = EP;
    }
}

__global__ void scan_apply_kernel() {
    __shared__ int sh[512];
    int b = blockIdx.x, t = threadIdx.x;
    int i = b * 512 + t;
    int v = (i < GN) ? d_rowcnt[i] : 0;
    sh[t] = v; __syncthreads();
    for (int off = 1; off < 512; off <<= 1) {
        int a = (t >= off) ? sh[t - off] : 0;
        __syncthreads();
        sh[t] += a;
        __syncthreads();
    }
    if (i < GN) {
        int excl = sh[t] - v + d_chunksum[b];
        d_rowstart[i] = excl;
        d_rowfill[i]  = excl;
    }
}

__global__ void scatter_kernel(const void* __restrict__ ei) {
    int i = blockIdx.x * blockDim.x + threadIdx.x;
    if (i >= EP) return;
    int is64 = d_is64;
    int ss, dd;
    if (i < GE) { ss = edge_at(ei, i, is64); dd = edge_at(ei, GE + i, is64); }
    else        { ss = i - GE; dd = ss; }
    int pos = atomicAdd(&d_rowfill[dd], 1);
    d_csrsrc[pos] = ss;
}

// ---------------- tf32x3 tensor-core GEMM (double-buffered) -------------
__device__ __forceinline__ void tf32_split(float x, float& hi, float& lo) {
    unsigned u;
    asm("cvt.rna.tf32.f32 %0, %1;" : "=r"(u) : "f"(x));
    hi = __uint_as_float(u);
    float r = x - hi;
    unsigned v;
    asm("cvt.rna.tf32.f32 %0, %1;" : "=r"(v) : "f"(r));
    lo = __uint_as_float(v);
}

__device__ __forceinline__ void mma_tf32(float* c,
                                         float a0, float a1, float a2, float a3,
                                         float b0, float b1) {
    asm("mma.sync.aligned.m16n8k8.row.col.f32.tf32.tf32.f32 "
        "{%0,%1,%2,%3}, {%4,%5,%6,%7}, {%8,%9}, {%0,%1,%2,%3};"
        : "+f"(c[0]), "+f"(c[1]), "+f"(c[2]), "+f"(c[3])
        : "r"(__float_as_uint(a0)), "r"(__float_as_uint(a1)),
          "r"(__float_as_uint(a2)), "r"(__float_as_uint(a3)),
          "r"(__float_as_uint(b0)), "r"(__float_as_uint(b1)));
}

#define SP 136   // smem pitch (floats)

__global__ void __launch_bounds__(256) gemm_kernel(
    const float* __restrict__ x_in,
    const float* __restrict__ Wl, const float* __restrict__ bl,
    const float* __restrict__ Wr, const float* __restrict__ br,
    int use_h)
{
    const float* A = use_h ? d_h : x_in;
    int mat = blockIdx.y;
    const float* W    = mat ? Wr : Wl;
    const float* bias = mat ? br : bl;
    float* O          = mat ? d_xr : d_xl;
    int row0 = blockIdx.x * 128;

    __shared__ float As_hi[2][8 * SP];
    __shared__ float As_lo[2][8 * SP];
    __shared__ float Bs_hi[2][8 * SP];
    __shared__ float Bs_lo[2][8 * SP];

    int tid  = threadIdx.x;
    int w    = tid >> 5;
    int lane = tid & 31;
    int g    = lane >> 2;
    int t4   = lane & 3;
    int rw   = (w & 3) * 32;
    int cw   = (w >> 2) * 64;

    int lrow = tid >> 1;
    int lq   = tid & 1;

    bool okA = (row0 + lrow) < GN;
    const float* Aptr = A + (size_t)(row0 + lrow) * 128 + lq * 4;
    const float* Wptr = W + (size_t)lrow * 128 + lq * 4;

    float acc[2][8][4];
    #pragma unroll
    for (int m = 0; m < 2; m++)
        #pragma unroll
        for (int n = 0; n < 8; n++)
            #pragma unroll
            for (int q = 0; q < 4; q++) acc[m][n][q] = 0.f;

    // stage k-chunk 0 into buffer 0
    {
        float4 av = okA ? *(const float4*)Aptr : make_float4(0.f, 0.f, 0.f, 0.f);
        float4 wv = *(const float4*)Wptr;
        float ah[4], al[4], wh[4], wl[4];
        tf32_split(av.x, ah[0], al[0]); tf32_split(av.y, ah[1], al[1]);
        tf32_split(av.z, ah[2], al[2]); tf32_split(av.w, ah[3], al[3]);
        tf32_split(wv.x, wh[0], wl[0]); tf32_split(wv.y, wh[1], wl[1]);
        tf32_split(wv.z, wh[2], wl[2]); tf32_split(wv.w, wh[3], wl[3]);
        #pragma unroll
        for (int m = 0; m < 4; m++) {
            int k = lq * 4 + m;
            As_hi[0][k * SP + lrow] = ah[m];
            As_lo[0][k * SP + lrow] = al[m];
            Bs_hi[0][k * SP + lrow] = wh[m];
            Bs_lo[0][k * SP + lrow] = wl[m];
        }
    }
    __syncthreads();

    for (int kc = 0; kc < 16; kc++) {
        int p = kc & 1;

        float4 av, wv;
        if (kc < 15) {
            av = okA ? *(const float4*)(Aptr + (kc + 1) * 8)
                     : make_float4(0.f, 0.f, 0.f, 0.f);
            wv = *(const float4*)(Wptr + (kc + 1) * 8);
        }

        // fragments from buffer p
        float Ah[2][4], Al[2][4];
        #pragma unroll
        for (int m = 0; m < 2; m++) {
            int rb = rw + m * 16;
            Ah[m][0] = As_hi[p][t4 * SP + rb + g];
            Ah[m][1] = As_hi[p][t4 * SP + rb + g + 8];
            Ah[m][2] = As_hi[p][(t4 + 4) * SP + rb + g];
            Ah[m][3] = As_hi[p][(t4 + 4) * SP + rb + g + 8];
            Al[m][0] = As_lo[p][t4 * SP + rb + g];
            Al[m][1] = As_lo[p][t4 * SP + rb + g + 8];
            Al[m][2] = As_lo[p][(t4 + 4) * SP + rb + g];
            Al[m][3] = As_lo[p][(t4 + 4) * SP + rb + g + 8];
        }

        #pragma unroll
        for (int n = 0; n < 8; n++) {
            int cb = cw + n * 8;
            float bh0 = Bs_hi[p][t4 * SP + cb + g];
            float bh1 = Bs_hi[p][(t4 + 4) * SP + cb + g];
            float bl0 = Bs_lo[p][t4 * SP + cb + g];
            float bl1 = Bs_lo[p][(t4 + 4) * SP + cb + g];
            #pragma unroll
            for (int m = 0; m < 2; m++) {
                mma_tf32(acc[m][n], Ah[m][0], Ah[m][1], Ah[m][2], Ah[m][3], bh0, bh1);
                mma_tf32(acc[m][n], Ah[m][0], Ah[m][1], Ah[m][2], Ah[m][3], bl0, bl1);
                mma_tf32(acc[m][n], Al[m][0], Al[m][1], Al[m][2], Al[m][3], bh0, bh1);
            }
        }

        if (kc < 15) {
            float ah[4], al[4], wh[4], wl[4];
            tf32_split(av.x, ah[0], al[0]); tf32_split(av.y, ah[1], al[1]);
            tf32_split(av.z, ah[2], al[2]); tf32_split(av.w, ah[3], al[3]);
            tf32_split(wv.x, wh[0], wl[0]); tf32_split(wv.y, wh[1], wl[1]);
            tf32_split(wv.z, wh[2], wl[2]); tf32_split(wv.w, wh[3], wl[3]);
            int q = 1 - p;
            #pragma unroll
            for (int m = 0; m < 4; m++) {
                int k = lq * 4 + m;
                As_hi[q][k * SP + lrow] = ah[m];
                As_lo[q][k * SP + lrow] = al[m];
                Bs_hi[q][k * SP + lrow] = wh[m];
                Bs_lo[q][k * SP + lrow] = wl[m];
            }
            __syncthreads();
        }
    }

    #pragma unroll
    for (int m = 0; m < 2; m++) {
        int r0 = row0 + rw + m * 16 + g;
        int r1 = r0 + 8;
        #pragma unroll
        for (int n = 0; n < 8; n++) {
            int cb = cw + n * 8 + t4 * 2;
            float b0 = bias[cb], b1 = bias[cb + 1];
            if (r0 < GN) {
                float2 v0 = make_float2(acc[m][n][0] + b0, acc[m][n][1] + b1);
                *(float2*)&O[(size_t)r0 * 128 + cb] = v0;
            }
            if (r1 < GN) {
                float2 v1 = make_float2(acc[m][n][2] + b0, acc[m][n][3] + b1);
                *(float2*)&O[(size_t)r1 * 128 + cb] = v1;
            }
        }
    }
}

// ---------------- fused GATv2 (4-edge unroll, warp per row) -------------
__device__ __forceinline__ float edge_logit(const float4& xv, const float4& xrv,
                                            const float4& attv) {
    float v, lg;
    v = xv.x + xrv.x; v = v > 0.f ? v : 0.2f * v; lg = v * attv.x;
    v = xv.y + xrv.y; v = v > 0.f ? v : 0.2f * v; lg = fmaf(v, attv.y, lg);
    v = xv.z + xrv.z; v = v > 0.f ? v : 0.2f * v; lg = fmaf(v, attv.z, lg);
    v = xv.w + xrv.w; v = v > 0.f ? v : 0.2f * v; lg = fmaf(v, attv.w, lg);
    return lg;
}

__global__ void __launch_bounds__(256) gat_row_kernel(const float* __restrict__ att,
                                                      const float* __restrict__ bias)
{
    int row = blockIdx.x * 8 + (threadIdx.x >> 5);
    if (row >= GN) return;
    int lane = threadIdx.x & 31;

    float4 attv = ((const float4*)att)[lane];
    float4 xrv  = ((const float4*)d_xr)[(size_t)row * 32 + lane];

    int e0 = d_rowstart[row], e1 = d_rowstart[row + 1];
    int cnt = e1 - e0;

    float mx = -1e30f, dn = 0.f;
    float4 ac = make_float4(0.f, 0.f, 0.f, 0.f);

    const float4* XL = (const float4*)d_xl;

    float4 xv0, xv1, xv2, xv3;
    if (cnt >= 4) {
        xv0 = XL[(size_t)d_csrsrc[e0]     * 32 + lane];
        xv1 = XL[(size_t)d_csrsrc[e0 + 1] * 32 + lane];
        xv2 = XL[(size_t)d_csrsrc[e0 + 2] * 32 + lane];
        xv3 = XL[(size_t)d_csrsrc[e0 + 3] * 32 + lane];
    }

    int j = e0;
    for (; j + 3 < e1; j += 4) {
        int p0 = (j + 4 < e1) ? d_csrsrc[j + 4] : 0;
        int p1 = (j + 5 < e1) ? d_csrsrc[j + 5] : 0;
        int p2 = (j + 6 < e1) ? d_csrsrc[j + 6] : 0;
        int p3 = (j + 7 < e1) ? d_csrsrc[j + 7] : 0;
        float4 xn0 = XL[(size_t)p0 * 32 + lane];
        float4 xn1 = XL[(size_t)p1 * 32 + lane];
        float4 xn2 = XL[(size_t)p2 * 32 + lane];
        float4 xn3 = XL[(size_t)p3 * 32 + lane];

        float lg0 = edge_logit(xv0, xrv, attv);
        float lg1 = edge_logit(xv1, xrv, attv);
        float lg2 = edge_logit(xv2, xrv, attv);
        float lg3 = edge_logit(xv3, xrv, attv);
        lg0 += __shfl_xor_sync(0xffffffffu, lg0, 4);
        lg1 += __shfl_xor_sync(0xffffffffu, lg1, 4);
        lg2 += __shfl_xor_sync(0xffffffffu, lg2, 4);
        lg3 += __shfl_xor_sync(0xffffffffu, lg3, 4);
        lg0 += __shfl_xor_sync(0xffffffffu, lg0, 2);
        lg1 += __shfl_xor_sync(0xffffffffu, lg1, 2);
        lg2 += __shfl_xor_sync(0xffffffffu, lg2, 2);
        lg3 += __shfl_xor_sync(0xffffffffu, lg3, 2);
        lg0 += __shfl_xor_sync(0xffffffffu, lg0, 1);
        lg1 += __shfl_xor_sync(0xffffffffu, lg1, 1);
        lg2 += __shfl_xor_sync(0xffffffffu, lg2, 1);
        lg3 += __shfl_xor_sync(0xffffffffu, lg3, 1);

        // 4-edge local softmax
        float m = fmaxf(fmaxf(lg0, lg1), fmaxf(lg2, lg3));
        float w0 = __expf(lg0 - m);
        float w1 = __expf(lg1 - m);
        float w2 = __expf(lg2 - m);
        float w3 = __expf(lg3 - m);
        float pd = (w0 + w1) + (w2 + w3);
        float4 pa;
        pa.x = fmaf(w0, xv0.x, w1 * xv1.x) + fmaf(w2, xv2.x, w3 * xv3.x);
        pa.y = fmaf(w0, xv0.y, w1 * xv1.y) + fmaf(w2, xv2.y, w3 * xv3.y);
        pa.z = fmaf(w0, xv0.z, w1 * xv1.z) + fmaf(w2, xv2.z, w3 * xv3.z);
        pa.w = fmaf(w0, xv0.w, w1 * xv1.w) + fmaf(w2, xv2.w, w3 * xv3.w);

        // merge into running state
        float nm = fmaxf(mx, m);
        float a  = __expf(mx - nm);
        float b  = __expf(m - nm);
        dn = fmaf(dn, a, pd * b);
        ac.x = fmaf(ac.x, a, pa.x * b);
        ac.y = fmaf(ac.y, a, pa.y * b);
        ac.z = fmaf(ac.z, a, pa.z * b);
        ac.w = fmaf(ac.w, a, pa.w * b);
        mx = nm;

        xv0 = xn0; xv1 = xn1; xv2 = xn2; xv3 = xn3;
    }

    for (; j < e1; j++) {
        int s = d_csrsrc[j];
        float4 xv = XL[(size_t)s * 32 + lane];
        float lg = edge_logit(xv, xrv, attv);
        lg += __shfl_xor_sync(0xffffffffu, lg, 4);
        lg += __shfl_xor_sync(0xffffffffu, lg, 2);
        lg += __shfl_xor_sync(0xffffffffu, lg, 1);
        float nm = fmaxf(mx, lg);
        float a  = __expf(mx - nm);
        float w  = __expf(lg - nm);
        dn = fmaf(dn, a, w);
        ac.x = fmaf(ac.x, a, w * xv.x);
        ac.y = fmaf(ac.y, a, w * xv.y);
        ac.z = fmaf(ac.z, a, w * xv.z);
        ac.w = fmaf(ac.w, a, w * xv.w);
        mx = nm;
    }

    float inv = 1.f / dn;
    float4 bv = ((const float4*)bias)[lane];
    float4 o;
    o.x = fmaxf(fmaf(ac.x, inv, bv.x), 0.f);
    o.y = fmaxf(fmaf(ac.y, inv, bv.y), 0.f);
    o.z = fmaxf(fmaf(ac.z, inv, bv.z), 0.f);
    o.w = fmaxf(fmaf(ac.w, inv, bv.w), 0.f);
    ((float4*)d_h)[(size_t)row * 32 + lane] = o;
}

// ---------------- pooling ----------------
__global__ void zero_pool_kernel() {
    int i = blockIdx.x * blockDim.x + threadIdx.x;
    if (i < GG * 128) d_pool[i] = 0.f;
    if (i < GG) d_cnt[i] = 0.f;
}

__global__ void count_kernel(const void* __restrict__ batch) {
    int i = blockIdx.x * blockDim.x + threadIdx.x;
    if (i >= GN) return;
    int g = edge_at(batch, i, d_is64);
    atomicAdd(&d_cnt[g], 1.f);
}

__global__ void pool_kernel(const void* __restrict__ batch) {
    const int CHUNK = 256;
    int n0 = blockIdx.x * CHUNK;
    int n1 = n0 + CHUNK; if (n1 > GN) n1 = GN;
    int col = threadIdx.x;
    int is64 = d_is64;
    int curg = -1;
    float acc = 0.f;
    for (int n = n0; n < n1; n++) {
        int g = edge_at(batch, n, is64);
        if (g != curg) {
            if (curg >= 0) atomicAdd(&d_pool[curg * 128 + col], acc);
            curg = g; acc = 0.f;
        }
        acc += d_h[(size_t)n * 128 + col];
    }
    if (curg >= 0) atomicAdd(&d_pool[curg * 128 + col], acc);
}

// ---------------- classifier ----------------
__global__ void classifier_kernel(
    const float* __restrict__ Wc1, const float* __restrict__ bc1,
    const float* __restrict__ Wc2, const float* __restrict__ bc2,
    float* __restrict__ out)
{
    int g = threadIdx.x;
    if (g >= GG) return;
    float inv = 1.f / fmaxf(d_cnt[g], 1.f);
    float z[8];
    #pragma unroll
    for (int j = 0; j < 8; j++) {
        float s = 0.f;
        for (int k = 0; k < 128; k++)
            s += d_pool[g * 128 + k] * Wc1[j * 128 + k];
        s = s * inv + bc1[j];
        z[j] = fmaxf(s, 0.f);
    }
    float o = bc2[0];
    #pragma unroll
    for (int j = 0; j < 8; j++) o += z[j] * Wc2[j];
    out[g] = o;
}

// ---------------- launch ----------------
extern "C" void kernel_launch(void* const* d_in, const int* in_sizes, int n_in,
                              void* d_out, int out_size) {
    const float* x     = (const float*)d_in[0];
    const void*  ei    = d_in[1];
    const void*  batch = d_in[2];
    const float* Wl0 = (const float*)d_in[3];
    const float* bl0 = (const float*)d_in[4];
    const float* Wr0 = (const float*)d_in[5];
    const float* br0 = (const float*)d_in[6];
    const float* at0 = (const float*)d_in[7];
    const float* bi0 = (const float*)d_in[8];
    const float* Wl1 = (const float*)d_in[9];
    const float* bl1 = (const float*)d_in[10];
    const float* Wr1 = (const float*)d_in[11];
    const float* br1 = (const float*)d_in[12];
    const float* at1 = (const float*)d_in[13];
    const float* bi1 = (const float*)d_in[14];
    const float* Wc1 = (const float*)d_in[15];
    const float* bc1 = (const float*)d_in[16];
    const float* Wc2 = (const float*)d_in[17];
    const float* bc2 = (const float*)d_in[18];
    float* out = (float*)d_out;

    const dim3 GEMM_GRID((GN + 127) / 128, 2);

    // gemm is the 4th launch -> profiled by the ncu window.
    detect_kernel<<<1, 32>>>((const int*)ei);                 // 1
    zero_cnt_kernel<<<(GN + 255) / 256, 256>>>();             // 2
    hist_kernel<<<(EP + 255) / 256, 256>>>(ei);               // 3
    gemm_kernel<<<GEMM_GRID, 256>>>(x, Wl0, bl0, Wr0, br0, 0);// 4 (profiled)
    chunk_sum_kernel<<<NCH, 256>>>();                         // 5
    tops_kernel<<<1, 32>>>();                                 // 6
    scan_apply_kernel<<<NCH, 512>>>();                        // 7
    scatter_kernel<<<(EP + 255) / 256, 256>>>(ei);            // 8

    gat_row_kernel<<<(GN + 7) / 8, 256>>>(at0, bi0);
    gemm_kernel<<<GEMM_GRID, 256>>>(x, Wl1, bl1, Wr1, br1, 1);
    gat_row_kernel<<<(GN + 7) / 8, 256>>>(at1, bi1);

    zero_pool_kernel<<<(GG * 128 + 255) / 256, 256>>>();
    count_kernel<<<(GN + 255) / 256, 256>>>(batch);
    pool_kernel<<<(GN + 255) / 256, 128>>>(batch);
    classifier_kernel<<<1, 64>>>(Wc1, bc1, Wc2, bc2, out);
}

// round 10
// speedup vs baseline: 2.1227x; 1.0218x over previous
#include <cuda_runtime.h>
#include <cuda_fp16.h>

#define GN 50000
#define GE 800000
#define EP 850000   // GE + GN self-loops
#define GG 64
#define NCH 98      // ceil(GN/512)

// ---------------- scratch (device globals; no allocation) ----------------
__device__ __align__(16) __half d_xl16[GN * 128];
__device__ __align__(16) float  d_xr[GN * 128];
__device__ __align__(16) float  d_h[GN * 128];
__device__ int   d_rowcnt[GN];
__device__ int   d_rowstart[GN + 1];
__device__ int   d_rowfill[GN];
__device__ int   d_csrsrc[EP];
__device__ int   d_chunksum[NCH];
__device__ float d_pool[GG * 128];
__device__ float d_cnt[GG];
__device__ int   d_is64;

// ---------------- int32/int64 width detection ----------------
__global__ void detect_kernel(const int* __restrict__ ei32) {
    if (threadIdx.x == 0 && blockIdx.x == 0) {
        int any = 0;
        #pragma unroll
        for (int i = 1; i < 128; i += 2) any |= ei32[i];
        d_is64 = (any == 0) ? 1 : 0;
    }
}

__device__ __forceinline__ int edge_at(const void* ei, int idx, int is64) {
    return is64 ? (int)((const long long*)ei)[idx] : ((const int*)ei)[idx];
}

// ---------------- CSR build: hist -> scan -> scatter ----------------
__global__ void zero_cnt_kernel() {
    int i = blockIdx.x * blockDim.x + threadIdx.x;
    if (i < GN) d_rowcnt[i] = 0;
}

__global__ void hist_kernel(const void* __restrict__ ei) {
    int i = blockIdx.x * blockDim.x + threadIdx.x;
    if (i >= EP) return;
    int is64 = d_is64;
    int dd = (i < GE) ? edge_at(ei, GE + i, is64) : (i - GE);
    atomicAdd(&d_rowcnt[dd], 1);
}

__global__ void chunk_sum_kernel() {
    __shared__ int sh[256];
    int b = blockIdx.x, t = threadIdx.x;
    int base = b * 512;
    int v = 0;
    int i0 = base + t;       if (i0 < GN) v += d_rowcnt[i0];
    int i1 = base + 256 + t; if (i1 < GN) v += d_rowcnt[i1];
    sh[t] = v; __syncthreads();
    for (int off = 128; off; off >>= 1) {
        if (t < off) sh[t] += sh[t + off];
        __syncthreads();
    }
    if (t == 0) d_chunksum[b] = sh[0];
}

__global__ void tops_kernel() {
    if (threadIdx.x == 0) {
        int run = 0;
        for (int b = 0; b < NCH; b++) { int t = d_chunksum[b]; d_chunksum[b] = run; run += t; }
        d_rowstart[GN] = EP;
    }
}

__global__ void scan_apply_kernel() {
    __shared__ int sh[512];
    int b = blockIdx.x, t = threadIdx.x;
    int i = b * 512 + t;
    int v = (i < GN) ? d_rowcnt[i] : 0;
    sh[t] = v; __syncthreads();
    for (int off = 1; off < 512; off <<= 1) {
        int a = (t >= off) ? sh[t - off] : 0;
        __syncthreads();
        sh[t] += a;
        __syncthreads();
    }
    if (i < GN) {
        int excl = sh[t] - v + d_chunksum[b];
        d_rowstart[i] = excl;
        d_rowfill[i]  = excl;
    }
}

__global__ void scatter_kernel(const void* __restrict__ ei) {
    int i = blockIdx.x * blockDim.x + threadIdx.x;
    if (i >= EP) return;
    int is64 = d_is64;
    int ss, dd;
    if (i < GE) { ss = edge_at(ei, i, is64); dd = edge_at(ei, GE + i, is64); }
    else        { ss = i - GE; dd = ss; }
    int pos = atomicAdd(&d_rowfill[dd], 1);
    d_csrsrc[pos] = ss;
}

// ---------------- tf32x3 tensor-core GEMM (double-buffered) -------------
__device__ __forceinline__ void tf32_split(float x, float& hi, float& lo) {
    unsigned u;
    asm("cvt.rna.tf32.f32 %0, %1;" : "=r"(u) : "f"(x));
    hi = __uint_as_float(u);
    float r = x - hi;
    unsigned v;
    asm("cvt.rna.tf32.f32 %0, %1;" : "=r"(v) : "f"(r));
    lo = __uint_as_float(v);
}

__device__ __forceinline__ void mma_tf32(float* c,
                                         float a0, float a1, float a2, float a3,
                                         float b0, float b1) {
    asm("mma.sync.aligned.m16n8k8.row.col.f32.tf32.tf32.f32 "
        "{%0,%1,%2,%3}, {%4,%5,%6,%7}, {%8,%9}, {%0,%1,%2,%3};"
        : "+f"(c[0]), "+f"(c[1]), "+f"(c[2]), "+f"(c[3])
        : "r"(__float_as_uint(a0)), "r"(__float_as_uint(a1)),
          "r"(__float_as_uint(a2)), "r"(__float_as_uint(a3)),
          "r"(__float_as_uint(b0)), "r"(__float_as_uint(b1)));
}

#define SP 136   // smem pitch (floats)

__global__ void __launch_bounds__(256) gemm_kernel(
    const float* __restrict__ x_in,
    const float* __restrict__ Wl, const float* __restrict__ bl,
    const float* __restrict__ Wr, const float* __restrict__ br,
    int use_h)
{
    const float* A = use_h ? d_h : x_in;
    int mat = blockIdx.y;
    const float* W    = mat ? Wr : Wl;
    const float* bias = mat ? br : bl;
    int row0 = blockIdx.x * 128;

    __shared__ float As_hi[2][8 * SP];
    __shared__ float As_lo[2][8 * SP];
    __shared__ float Bs_hi[2][8 * SP];
    __shared__ float Bs_lo[2][8 * SP];

    int tid  = threadIdx.x;
    int w    = tid >> 5;
    int lane = tid & 31;
    int g    = lane >> 2;
    int t4   = lane & 3;
    int rw   = (w & 3) * 32;
    int cw   = (w >> 2) * 64;

    int lrow = tid >> 1;
    int lq   = tid & 1;

    bool okA = (row0 + lrow) < GN;
    const float* Aptr = A + (size_t)(row0 + lrow) * 128 + lq * 4;
    const float* Wptr = W + (size_t)lrow * 128 + lq * 4;

    float acc[2][8][4];
    #pragma unroll
    for (int m = 0; m < 2; m++)
        #pragma unroll
        for (int n = 0; n < 8; n++)
            #pragma unroll
            for (int q = 0; q < 4; q++) acc[m][n][q] = 0.f;

    {
        float4 av = okA ? *(const float4*)Aptr : make_float4(0.f, 0.f, 0.f, 0.f);
        float4 wv = *(const float4*)Wptr;
        float ah[4], al[4], wh[4], wl[4];
        tf32_split(av.x, ah[0], al[0]); tf32_split(av.y, ah[1], al[1]);
        tf32_split(av.z, ah[2], al[2]); tf32_split(av.w, ah[3], al[3]);
        tf32_split(wv.x, wh[0], wl[0]); tf32_split(wv.y, wh[1], wl[1]);
        tf32_split(wv.z, wh[2], wl[2]); tf32_split(wv.w, wh[3], wl[3]);
        #pragma unroll
        for (int m = 0; m < 4; m++) {
            int k = lq * 4 + m;
            As_hi[0][k * SP + lrow] = ah[m];
            As_lo[0][k * SP + lrow] = al[m];
            Bs_hi[0][k * SP + lrow] = wh[m];
            Bs_lo[0][k * SP + lrow] = wl[m];
        }
    }
    __syncthreads();

    for (int kc = 0; kc < 16; kc++) {
        int p = kc & 1;

        float4 av, wv;
        if (kc < 15) {
            av = okA ? *(const float4*)(Aptr + (kc + 1) * 8)
                     : make_float4(0.f, 0.f, 0.f, 0.f);
            wv = *(const float4*)(Wptr + (kc + 1) * 8);
        }

        float Ah[2][4], Al[2][4];
        #pragma unroll
        for (int m = 0; m < 2; m++) {
            int rb = rw + m * 16;
            Ah[m][0] = As_hi[p][t4 * SP + rb + g];
            Ah[m][1] = As_hi[p][t4 * SP + rb + g + 8];
            Ah[m][2] = As_hi[p][(t4 + 4) * SP + rb + g];
            Ah[m][3] = As_hi[p][(t4 + 4) * SP + rb + g + 8];
            Al[m][0] = As_lo[p][t4 * SP + rb + g];
            Al[m][1] = As_lo[p][t4 * SP + rb + g + 8];
            Al[m][2] = As_lo[p][(t4 + 4) * SP + rb + g];
            Al[m][3] = As_lo[p][(t4 + 4) * SP + rb + g + 8];
        }

        #pragma unroll
        for (int n = 0; n < 8; n++) {
            int cb = cw + n * 8;
            float bh0 = Bs_hi[p][t4 * SP + cb + g];
            float bh1 = Bs_hi[p][(t4 + 4) * SP + cb + g];
            float bl0 = Bs_lo[p][t4 * SP + cb + g];
            float bl1 = Bs_lo[p][(t4 + 4) * SP + cb + g];
            #pragma unroll
            for (int m = 0; m < 2; m++) {
                mma_tf32(acc[m][n], Ah[m][0], Ah[m][1], Ah[m][2], Ah[m][3], bh0, bh1);
                mma_tf32(acc[m][n], Ah[m][0], Ah[m][1], Ah[m][2], Ah[m][3], bl0, bl1);
                mma_tf32(acc[m][n], Al[m][0], Al[m][1], Al[m][2], Al[m][3], bh0, bh1);
            }
        }

        if (kc < 15) {
            float ah[4], al[4], wh[4], wl[4];
            tf32_split(av.x, ah[0], al[0]); tf32_split(av.y, ah[1], al[1]);
            tf32_split(av.z, ah[2], al[2]); tf32_split(av.w, ah[3], al[3]);
            tf32_split(wv.x, wh[0], wl[0]); tf32_split(wv.y, wh[1], wl[1]);
            tf32_split(wv.z, wh[2], wl[2]); tf32_split(wv.w, wh[3], wl[3]);
            int q = 1 - p;
            #pragma unroll
            for (int m = 0; m < 4; m++) {
                int k = lq * 4 + m;
                As_hi[q][k * SP + lrow] = ah[m];
                As_lo[q][k * SP + lrow] = al[m];
                Bs_hi[q][k * SP + lrow] = wh[m];
                Bs_lo[q][k * SP + lrow] = wl[m];
            }
            __syncthreads();
        }
    }

    // epilogue: mat==0 -> fp16 xl only; mat==1 -> fp32 xr
    #pragma unroll
    for (int m = 0; m < 2; m++) {
        int r0 = row0 + rw + m * 16 + g;
        int r1 = r0 + 8;
        #pragma unroll
        for (int n = 0; n < 8; n++) {
            int cb = cw + n * 8 + t4 * 2;
            float b0 = bias[cb], b1 = bias[cb + 1];
            float v00 = acc[m][n][0] + b0, v01 = acc[m][n][1] + b1;
            float v10 = acc[m][n][2] + b0, v11 = acc[m][n][3] + b1;
            if (mat == 0) {
                if (r0 < GN)
                    *(__half2*)&d_xl16[(size_t)r0 * 128 + cb] = __floats2half2_rn(v00, v01);
                if (r1 < GN)
                    *(__half2*)&d_xl16[(size_t)r1 * 128 + cb] = __floats2half2_rn(v10, v11);
            } else {
                if (r0 < GN)
                    *(float2*)&d_xr[(size_t)r0 * 128 + cb] = make_float2(v00, v01);
                if (r1 < GN)
                    *(float2*)&d_xr[(size_t)r1 * 128 + cb] = make_float2(v10, v11);
            }
        }
    }
}

// ---------------- fused GATv2 (4-edge unroll, fp16 xl, warp per row) ----
__device__ __forceinline__ float4 xl_load(const uint2* __restrict__ XL16,
                                          int s, int lane) {
    uint2 v = XL16[(size_t)s * 32 + lane];
    float2 f01 = __half22float2(*(__half2*)&v.x);
    float2 f23 = __half22float2(*(__half2*)&v.y);
    return make_float4(f01.x, f01.y, f23.x, f23.y);
}

__device__ __forceinline__ float edge_logit(const float4& xv, const float4& xrv,
                                            const float4& attv) {
    float v, lg;
    v = xv.x + xrv.x; v = v > 0.f ? v : 0.2f * v; lg = v * attv.x;
    v = xv.y + xrv.y; v = v > 0.f ? v : 0.2f * v; lg = fmaf(v, attv.y, lg);
    v = xv.z + xrv.z; v = v > 0.f ? v : 0.2f * v; lg = fmaf(v, attv.z, lg);
    v = xv.w + xrv.w; v = v > 0.f ? v : 0.2f * v; lg = fmaf(v, attv.w, lg);
    return lg;
}

__global__ void __launch_bounds__(256) gat_row_kernel(const float* __restrict__ att,
                                                      const float* __restrict__ bias)
{
    int row = blockIdx.x * 8 + (threadIdx.x >> 5);
    if (row >= GN) return;
    int lane = threadIdx.x & 31;

    float4 attv = ((const float4*)att)[lane];
    float4 xrv  = ((const float4*)d_xr)[(size_t)row * 32 + lane];

    int e0 = d_rowstart[row], e1 = d_rowstart[row + 1];
    int cnt = e1 - e0;

    float mx = -1e30f, dn = 0.f;
    float4 ac = make_float4(0.f, 0.f, 0.f, 0.f);

    const uint2* XL16 = (const uint2*)d_xl16;

    float4 xv0, xv1, xv2, xv3;
    if (cnt >= 4) {
        xv0 = xl_load(XL16, d_csrsrc[e0],     lane);
        xv1 = xl_load(XL16, d_csrsrc[e0 + 1], lane);
        xv2 = xl_load(XL16, d_csrsrc[e0 + 2], lane);
        xv3 = xl_load(XL16, d_csrsrc[e0 + 3], lane);
    }

    int j = e0;
    for (; j + 3 < e1; j += 4) {
        int p0 = (j + 4 < e1) ? d_csrsrc[j + 4] : 0;
        int p1 = (j + 5 < e1) ? d_csrsrc[j + 5] : 0;
        int p2 = (j + 6 < e1) ? d_csrsrc[j + 6] : 0;
        int p3 = (j + 7 < e1) ? d_csrsrc[j + 7] : 0;
        float4 xn0 = xl_load(XL16, p0, lane);
        float4 xn1 = xl_load(XL16, p1, lane);
        float4 xn2 = xl_load(XL16, p2, lane);
        float4 xn3 = xl_load(XL16, p3, lane);

        float lg0 = edge_logit(xv0, xrv, attv);
        float lg1 = edge_logit(xv1, xrv, attv);
        float lg2 = edge_logit(xv2, xrv, attv);
        float lg3 = edge_logit(xv3, xrv, attv);
        lg0 += __shfl_xor_sync(0xffffffffu, lg0, 4);
        lg1 += __shfl_xor_sync(0xffffffffu, lg1, 4);
        lg2 += __shfl_xor_sync(0xffffffffu, lg2, 4);
        lg3 += __shfl_xor_sync(0xffffffffu, lg3, 4);
        lg0 += __shfl_xor_sync(0xffffffffu, lg0, 2);
        lg1 += __shfl_xor_sync(0xffffffffu, lg1, 2);
        lg2 += __shfl_xor_sync(0xffffffffu, lg2, 2);
        lg3 += __shfl_xor_sync(0xffffffffu, lg3, 2);
        lg0 += __shfl_xor_sync(0xffffffffu, lg0, 1);
        lg1 += __shfl_xor_sync(0xffffffffu, lg1, 1);
        lg2 += __shfl_xor_sync(0xffffffffu, lg2, 1);
        lg3 += __shfl_xor_sync(0xffffffffu, lg3, 1);

        float m = fmaxf(fmaxf(lg0, lg1), fmaxf(lg2, lg3));
        float w0 = __expf(lg0 - m);
        float w1 = __expf(lg1 - m);
        float w2 = __expf(lg2 - m);
        float w3 = __expf(lg3 - m);
        float pd = (w0 + w1) + (w2 + w3);
        float4 pa;
        pa.x = fmaf(w0, xv0.x, w1 * xv1.x) + fmaf(w2, xv2.x, w3 * xv3.x);
        pa.y = fmaf(w0, xv0.y, w1 * xv1.y) + fmaf(w2, xv2.y, w3 * xv3.y);
        pa.z = fmaf(w0, xv0.z, w1 * xv1.z) + fmaf(w2, xv2.z, w3 * xv3.z);
        pa.w = fmaf(w0, xv0.w, w1 * xv1.w) + fmaf(w2, xv2.w, w3 * xv3.w);

        float nm = fmaxf(mx, m);
        float a  = __expf(mx - nm);
        float b  = __expf(m - nm);
        dn = fmaf(dn, a, pd * b);
        ac.x = fmaf(ac.x, a, pa.x * b);
        ac.y = fmaf(ac.y, a, pa.y * b);
        ac.z = fmaf(ac.z, a, pa.z * b);
        ac.w = fmaf(ac.w, a, pa.w * b);
        mx = nm;

        xv0 = xn0; xv1 = xn1; xv2 = xn2; xv3 = xn3;
    }

    for (; j < e1; j++) {
        float4 xv = xl_load(XL16, d_csrsrc[j], lane);
        float lg = edge_logit(xv, xrv, attv);
        lg += __shfl_xor_sync(0xffffffffu, lg, 4);
        lg += __shfl_xor_sync(0xffffffffu, lg, 2);
        lg += __shfl_xor_sync(0xffffffffu, lg, 1);
        float nm = fmaxf(mx, lg);
        float a  = __expf(mx - nm);
        float w  = __expf(lg - nm);
        dn = fmaf(dn, a, w);
        ac.x = fmaf(ac.x, a, w * xv.x);
        ac.y = fmaf(ac.y, a, w * xv.y);
        ac.z = fmaf(ac.z, a, w * xv.z);
        ac.w = fmaf(ac.w, a, w * xv.w);
        mx = nm;
    }

    float inv = 1.f / dn;
    float4 bv = ((const float4*)bias)[lane];
    float4 o;
    o.x = fmaxf(fmaf(ac.x, inv, bv.x), 0.f);
    o.y = fmaxf(fmaf(ac.y, inv, bv.y), 0.f);
    o.z = fmaxf(fmaf(ac.z, inv, bv.z), 0.f);
    o.w = fmaxf(fmaf(ac.w, inv, bv.w), 0.f);
    ((float4*)d_h)[(size_t)row * 32 + lane] = o;
}

// ---------------- pooling ----------------
__global__ void zero_pool_kernel() {
    int i = blockIdx.x * blockDim.x + threadIdx.x;
    if (i < GG * 128) d_pool[i] = 0.f;
    if (i < GG) d_cnt[i] = 0.f;
}

__global__ void count_kernel(const void* __restrict__ batch) {
    int i = blockIdx.x * blockDim.x + threadIdx.x;
    if (i >= GN) return;
    int g = edge_at(batch, i, d_is64);
    atomicAdd(&d_cnt[g], 1.f);
}

__global__ void pool_kernel(const void* __restrict__ batch) {
    const int CHUNK = 256;
    int n0 = blockIdx.x * CHUNK;
    int n1 = n0 + CHUNK; if (n1 > GN) n1 = GN;
    int col = threadIdx.x;
    int is64 = d_is64;
    int curg = -1;
    float acc = 0.f;
    for (int n = n0; n < n1; n++) {
        int g = edge_at(batch, n, is64);
        if (g != curg) {
            if (curg >= 0) atomicAdd(&d_pool[curg * 128 + col], acc);
            curg = g; acc = 0.f;
        }
        acc += d_h[(size_t)n * 128 + col];
    }
    if (curg >= 0) atomicAdd(&d_pool[curg * 128 + col], acc);
}

// ---------------- classifier ----------------
__global__ void classifier_kernel(
    const float* __restrict__ Wc1, const float* __restrict__ bc1,
    const float* __restrict__ Wc2, const float* __restrict__ bc2,
    float* __restrict__ out)
{
    int g = threadIdx.x;
    if (g >= GG) return;
    float inv = 1.f / fmaxf(d_cnt[g], 1.f);
    float z[8];
    #pragma unroll
    for (int j = 0; j < 8; j++) {
        float s = 0.f;
        for (int k = 0; k < 128; k++)
            s += d_pool[g * 128 + k] * Wc1[j * 128 + k];
        s = s * inv + bc1[j];
        z[j] = fmaxf(s, 0.f);
    }
    float o = bc2[0];
    #pragma unroll
    for (int j = 0; j < 8; j++) o += z[j] * Wc2[j];
    out[g] = o;
}

// ---------------- launch ----------------
extern "C" void kernel_launch(void* const* d_in, const int* in_sizes, int n_in,
                              void* d_out, int out_size) {
    const float* x     = (const float*)d_in[0];
    const void*  ei    = d_in[1];
    const void*  batch = d_in[2];
    const float* Wl0 = (const float*)d_in[3];
    const float* bl0 = (const float*)d_in[4];
    const float* Wr0 = (const float*)d_in[5];
    const float* br0 = (const float*)d_in[6];
    const float* at0 = (const float*)d_in[7];
    const float* bi0 = (const float*)d_in[8];
    const float* Wl1 = (const float*)d_in[9];
    const float* bl1 = (const float*)d_in[10];
    const float* Wr1 = (const float*)d_in[11];
    const float* br1 = (const float*)d_in[12];
    const float* at1 = (const float*)d_in[13];
    const float* bi1 = (const float*)d_in[14];
    const float* Wc1 = (const float*)d_in[15];
    const float* bc1 = (const float*)d_in[16];
    const float* Wc2 = (const float*)d_in[17];
    const float* bc2 = (const float*)d_in[18];
    float* out = (float*)d_out;

    const dim3 GEMM_GRID((GN + 127) / 128, 2);

    detect_kernel<<<1, 32>>>((const int*)ei);                 // 1
    zero_cnt_kernel<<<(GN + 255) / 256, 256>>>();             // 2
    hist_kernel<<<(EP + 255) / 256, 256>>>(ei);               // 3
    gemm_kernel<<<GEMM_GRID, 256>>>(x, Wl0, bl0, Wr0, br0, 0);// 4 (profiled)
    chunk_sum_kernel<<<NCH, 256>>>();                         // 5
    tops_kernel<<<1, 32>>>();                                 // 6
    scan_apply_kernel<<<NCH, 512>>>();                        // 7
    scatter_kernel<<<(EP + 255) / 256, 256>>>(ei);            // 8

    gat_row_kernel<<<(GN + 7) / 8, 256>>>(at0, bi0);
    gemm_kernel<<<GEMM_GRID, 256>>>(x, Wl1, bl1, Wr1, br1, 1);
    gat_row_kernel<<<(GN + 7) / 8, 256>>>(at1, bi1);

    zero_pool_kernel<<<(GG * 128 + 255) / 256, 256>>>();
    count_kernel<<<(GN + 255) / 256, 256>>>(batch);
    pool_kernel<<<(GN + 255) / 256, 128>>>(batch);
    classifier_kernel<<<1, 64>>>(Wc1, bc1, Wc2, bc2, out);
}

// round 11
// speedup vs baseline: 2.1280x; 1.0025x over previous
#include <cuda_runtime.h>
#include <cuda_fp16.h>

#define GN 50000
#define GE 800000
#define EP 850000   // GE + GN self-loops
#define GG 64
#define NCH 98      // ceil(GN/512)

// ---------------- scratch (device globals; no allocation) ----------------
__device__ __align__(16) __half d_xl16[GN * 128];
__device__ __align__(16) float  d_xr[GN * 128];
__device__ __align__(16) float  d_h[GN * 128];
__device__ int   d_rowcnt[GN];
__device__ int   d_rowstart[GN + 1];
__device__ int   d_rowfill[GN];
__device__ int   d_csrsrc[EP];
__device__ int   d_chunksum[NCH];
__device__ float d_pool[GG * 128];
__device__ float d_cnt[GG];
__device__ int   d_is64;

// ---------------- int32/int64 width detection ----------------
__global__ void detect_kernel(const int* __restrict__ ei32) {
    if (threadIdx.x == 0 && blockIdx.x == 0) {
        int any = 0;
        #pragma unroll
        for (int i = 1; i < 128; i += 2) any |= ei32[i];
        d_is64 = (any == 0) ? 1 : 0;
    }
}

__device__ __forceinline__ int edge_at(const void* ei, int idx, int is64) {
    return is64 ? (int)((const long long*)ei)[idx] : ((const int*)ei)[idx];
}

// ---------------- CSR build: hist -> scan -> scatter ----------------
__global__ void zero_cnt_kernel() {
    int i = blockIdx.x * blockDim.x + threadIdx.x;
    if (i < GN) d_rowcnt[i] = 0;
}

__global__ void hist_kernel(const void* __restrict__ ei) {
    int i = blockIdx.x * blockDim.x + threadIdx.x;
    if (i >= EP) return;
    int is64 = d_is64;
    int dd = (i < GE) ? edge_at(ei, GE + i, is64) : (i - GE);
    atomicAdd(&d_rowcnt[dd], 1);
}

__global__ void chunk_sum_kernel() {
    __shared__ int sh[256];
    int b = blockIdx.x, t = threadIdx.x;
    int base = b * 512;
    int v = 0;
    int i0 = base + t;       if (i0 < GN) v += d_rowcnt[i0];
    int i1 = base + 256 + t; if (i1 < GN) v += d_rowcnt[i1];
    sh[t] = v; __syncthreads();
    for (int off = 128; off; off >>= 1) {
        if (t < off) sh[t] += sh[t + off];
        __syncthreads();
    }
    if (t == 0) d_chunksum[b] = sh[0];
}

// parallel exclusive scan of the 98 chunk sums (replaces serial tops)
__global__ void tops_kernel() {
    __shared__ int sh[128];
    int t = threadIdx.x;
    int v = (t < NCH) ? d_chunksum[t] : 0;
    sh[t] = v; __syncthreads();
    for (int off = 1; off < 128; off <<= 1) {
        int a = (t >= off) ? sh[t - off] : 0;
        __syncthreads();
        sh[t] += a;
        __syncthreads();
    }
    if (t < NCH) d_chunksum[t] = sh[t] - v;   // exclusive
    if (t == 0) d_rowstart[GN] = EP;
}

__global__ void scan_apply_kernel() {
    __shared__ int sh[512];
    int b = blockIdx.x, t = threadIdx.x;
    int i = b * 512 + t;
    int v = (i < GN) ? d_rowcnt[i] : 0;
    sh[t] = v; __syncthreads();
    for (int off = 1; off < 512; off <<= 1) {
        int a = (t >= off) ? sh[t - off] : 0;
        __syncthreads();
        sh[t] += a;
        __syncthreads();
    }
    if (i < GN) {
        int excl = sh[t] - v + d_chunksum[b];
        d_rowstart[i] = excl;
        d_rowfill[i]  = excl;
    }
}

__global__ void scatter_kernel(const void* __restrict__ ei) {
    int i = blockIdx.x * blockDim.x + threadIdx.x;
    if (i >= EP) return;
    int is64 = d_is64;
    int ss, dd;
    if (i < GE) { ss = edge_at(ei, i, is64); dd = edge_at(ei, GE + i, is64); }
    else        { ss = i - GE; dd = ss; }
    int pos = atomicAdd(&d_rowfill[dd], 1);
    d_csrsrc[pos] = ss;
}

// ---------------- tf32x3 tensor-core GEMM (double-buffered) -------------
__device__ __forceinline__ void tf32_split(float x, float& hi, float& lo) {
    unsigned u;
    asm("cvt.rna.tf32.f32 %0, %1;" : "=r"(u) : "f"(x));
    hi = __uint_as_float(u);
    float r = x - hi;
    unsigned v;
    asm("cvt.rna.tf32.f32 %0, %1;" : "=r"(v) : "f"(r));
    lo = __uint_as_float(v);
}

__device__ __forceinline__ void mma_tf32(float* c,
                                         float a0, float a1, float a2, float a3,
                                         float b0, float b1) {
    asm("mma.sync.aligned.m16n8k8.row.col.f32.tf32.tf32.f32 "
        "{%0,%1,%2,%3}, {%4,%5,%6,%7}, {%8,%9}, {%0,%1,%2,%3};"
        : "+f"(c[0]), "+f"(c[1]), "+f"(c[2]), "+f"(c[3])
        : "r"(__float_as_uint(a0)), "r"(__float_as_uint(a1)),
          "r"(__float_as_uint(a2)), "r"(__float_as_uint(a3)),
          "r"(__float_as_uint(b0)), "r"(__float_as_uint(b1)));
}

#define SP 136   // smem pitch (floats)

__global__ void __launch_bounds__(256) gemm_kernel(
    const float* __restrict__ x_in,
    const float* __restrict__ Wl, const float* __restrict__ bl,
    const float* __restrict__ Wr, const float* __restrict__ br,
    int use_h)
{
    const float* A = use_h ? d_h : x_in;
    int mat = blockIdx.y;
    const float* W    = mat ? Wr : Wl;
    const float* bias = mat ? br : bl;
    int row0 = blockIdx.x * 128;

    __shared__ float As_hi[2][8 * SP];
    __shared__ float As_lo[2][8 * SP];
    __shared__ float Bs_hi[2][8 * SP];
    __shared__ float Bs_lo[2][8 * SP];

    int tid  = threadIdx.x;
    int w    = tid >> 5;
    int lane = tid & 31;
    int g    = lane >> 2;
    int t4   = lane & 3;
    int rw   = (w & 3) * 32;
    int cw   = (w >> 2) * 64;

    int lrow = tid >> 1;
    int lq   = tid & 1;

    bool okA = (row0 + lrow) < GN;
    const float* Aptr = A + (size_t)(row0 + lrow) * 128 + lq * 4;
    const float* Wptr = W + (size_t)lrow * 128 + lq * 4;

    float acc[2][8][4];
    #pragma unroll
    for (int m = 0; m < 2; m++)
        #pragma unroll
        for (int n = 0; n < 8; n++)
            #pragma unroll
            for (int q = 0; q < 4; q++) acc[m][n][q] = 0.f;

    {
        float4 av = okA ? *(const float4*)Aptr : make_float4(0.f, 0.f, 0.f, 0.f);
        float4 wv = *(const float4*)Wptr;
        float ah[4], al[4], wh[4], wl[4];
        tf32_split(av.x, ah[0], al[0]); tf32_split(av.y, ah[1], al[1]);
        tf32_split(av.z, ah[2], al[2]); tf32_split(av.w, ah[3], al[3]);
        tf32_split(wv.x, wh[0], wl[0]); tf32_split(wv.y, wh[1], wl[1]);
        tf32_split(wv.z, wh[2], wl[2]); tf32_split(wv.w, wh[3], wl[3]);
        #pragma unroll
        for (int m = 0; m < 4; m++) {
            int k = lq * 4 + m;
            As_hi[0][k * SP + lrow] = ah[m];
            As_lo[0][k * SP + lrow] = al[m];
            Bs_hi[0][k * SP + lrow] = wh[m];
            Bs_lo[0][k * SP + lrow] = wl[m];
        }
    }
    __syncthreads();

    for (int kc = 0; kc < 16; kc++) {
        int p = kc & 1;

        float4 av, wv;
        if (kc < 15) {
            av = okA ? *(const float4*)(Aptr + (kc + 1) * 8)
                     : make_float4(0.f, 0.f, 0.f, 0.f);
            wv = *(const float4*)(Wptr + (kc + 1) * 8);
        }

        float Ah[2][4], Al[2][4];
        #pragma unroll
        for (int m = 0; m < 2; m++) {
            int rb = rw + m * 16;
            Ah[m][0] = As_hi[p][t4 * SP + rb + g];
            Ah[m][1] = As_hi[p][t4 * SP + rb + g + 8];
            Ah[m][2] = As_hi[p][(t4 + 4) * SP + rb + g];
            Ah[m][3] = As_hi[p][(t4 + 4) * SP + rb + g + 8];
            Al[m][0] = As_lo[p][t4 * SP + rb + g];
            Al[m][1] = As_lo[p][t4 * SP + rb + g + 8];
            Al[m][2] = As_lo[p][(t4 + 4) * SP + rb + g];
            Al[m][3] = As_lo[p][(t4 + 4) * SP + rb + g + 8];
        }

        #pragma unroll
        for (int n = 0; n < 8; n++) {
            int cb = cw + n * 8;
            float bh0 = Bs_hi[p][t4 * SP + cb + g];
            float bh1 = Bs_hi[p][(t4 + 4) * SP + cb + g];
            float bl0 = Bs_lo[p][t4 * SP + cb + g];
            float bl1 = Bs_lo[p][(t4 + 4) * SP + cb + g];
            #pragma unroll
            for (int m = 0; m < 2; m++) {
                mma_tf32(acc[m][n], Ah[m][0], Ah[m][1], Ah[m][2], Ah[m][3], bh0, bh1);
                mma_tf32(acc[m][n], Ah[m][0], Ah[m][1], Ah[m][2], Ah[m][3], bl0, bl1);
                mma_tf32(acc[m][n], Al[m][0], Al[m][1], Al[m][2], Al[m][3], bh0, bh1);
            }
        }

        if (kc < 15) {
            float ah[4], al[4], wh[4], wl[4];
            tf32_split(av.x, ah[0], al[0]); tf32_split(av.y, ah[1], al[1]);
            tf32_split(av.z, ah[2], al[2]); tf32_split(av.w, ah[3], al[3]);
            tf32_split(wv.x, wh[0], wl[0]); tf32_split(wv.y, wh[1], wl[1]);
            tf32_split(wv.z, wh[2], wl[2]); tf32_split(wv.w, wh[3], wl[3]);
            int q = 1 - p;
            #pragma unroll
            for (int m = 0; m < 4; m++) {
                int k = lq * 4 + m;
                As_hi[q][k * SP + lrow] = ah[m];
                As_lo[q][k * SP + lrow] = al[m];
                Bs_hi[q][k * SP + lrow] = wh[m];
                Bs_lo[q][k * SP + lrow] = wl[m];
            }
            __syncthreads();
        }
    }

    #pragma unroll
    for (int m = 0; m < 2; m++) {
        int r0 = row0 + rw + m * 16 + g;
        int r1 = r0 + 8;
        #pragma unroll
        for (int n = 0; n < 8; n++) {
            int cb = cw + n * 8 + t4 * 2;
            float b0 = bias[cb], b1 = bias[cb + 1];
            float v00 = acc[m][n][0] + b0, v01 = acc[m][n][1] + b1;
            float v10 = acc[m][n][2] + b0, v11 = acc[m][n][3] + b1;
            if (mat == 0) {
                if (r0 < GN)
                    *(__half2*)&d_xl16[(size_t)r0 * 128 + cb] = __floats2half2_rn(v00, v01);
                if (r1 < GN)
                    *(__half2*)&d_xl16[(size_t)r1 * 128 + cb] = __floats2half2_rn(v10, v11);
            } else {
                if (r0 < GN)
                    *(float2*)&d_xr[(size_t)r0 * 128 + cb] = make_float2(v00, v01);
                if (r1 < GN)
                    *(float2*)&d_xr[(size_t)r1 * 128 + cb] = make_float2(v10, v11);
            }
        }
    }
}

// ---------------- fused GATv2 (TWO warps per row, fp16 xl) --------------
__device__ __forceinline__ float4 xl_load(const uint2* __restrict__ XL16,
                                          int s, int lane) {
    uint2 v = XL16[(size_t)s * 32 + lane];
    float2 f01 = __half22float2(*(__half2*)&v.x);
    float2 f23 = __half22float2(*(__half2*)&v.y);
    return make_float4(f01.x, f01.y, f23.x, f23.y);
}

__device__ __forceinline__ float edge_logit(const float4& xv, const float4& xrv,
                                            const float4& attv) {
    float v, lg;
    v = xv.x + xrv.x; v = v > 0.f ? v : 0.2f * v; lg = v * attv.x;
    v = xv.y + xrv.y; v = v > 0.f ? v : 0.2f * v; lg = fmaf(v, attv.y, lg);
    v = xv.z + xrv.z; v = v > 0.f ? v : 0.2f * v; lg = fmaf(v, attv.z, lg);
    v = xv.w + xrv.w; v = v > 0.f ? v : 0.2f * v; lg = fmaf(v, attv.w, lg);
    return lg;
}

// process CSR range [s0,s1) for one row-half; returns (mx, dn, ac)
__device__ __forceinline__ void gat_half(const uint2* XL16, int s0, int s1,
                                         int lane, const float4& xrv,
                                         const float4& attv,
                                         float& mx, float& dn, float4& ac)
{
    mx = -1e30f; dn = 0.f;
    ac = make_float4(0.f, 0.f, 0.f, 0.f);
    int cnt = s1 - s0;

    float4 xv0, xv1, xv2, xv3;
    if (cnt >= 4) {
        xv0 = xl_load(XL16, d_csrsrc[s0],     lane);
        xv1 = xl_load(XL16, d_csrsrc[s0 + 1], lane);
        xv2 = xl_load(XL16, d_csrsrc[s0 + 2], lane);
        xv3 = xl_load(XL16, d_csrsrc[s0 + 3], lane);
    }

    int j = s0;
    for (; j + 3 < s1; j += 4) {
        int p0 = (j + 4 < s1) ? d_csrsrc[j + 4] : 0;
        int p1 = (j + 5 < s1) ? d_csrsrc[j + 5] : 0;
        int p2 = (j + 6 < s1) ? d_csrsrc[j + 6] : 0;
        int p3 = (j + 7 < s1) ? d_csrsrc[j + 7] : 0;
        float4 xn0 = xl_load(XL16, p0, lane);
        float4 xn1 = xl_load(XL16, p1, lane);
        float4 xn2 = xl_load(XL16, p2, lane);
        float4 xn3 = xl_load(XL16, p3, lane);

        float lg0 = edge_logit(xv0, xrv, attv);
        float lg1 = edge_logit(xv1, xrv, attv);
        float lg2 = edge_logit(xv2, xrv, attv);
        float lg3 = edge_logit(xv3, xrv, attv);
        lg0 += __shfl_xor_sync(0xffffffffu, lg0, 4);
        lg1 += __shfl_xor_sync(0xffffffffu, lg1, 4);
        lg2 += __shfl_xor_sync(0xffffffffu, lg2, 4);
        lg3 += __shfl_xor_sync(0xffffffffu, lg3, 4);
        lg0 += __shfl_xor_sync(0xffffffffu, lg0, 2);
        lg1 += __shfl_xor_sync(0xffffffffu, lg1, 2);
        lg2 += __shfl_xor_sync(0xffffffffu, lg2, 2);
        lg3 += __shfl_xor_sync(0xffffffffu, lg3, 2);
        lg0 += __shfl_xor_sync(0xffffffffu, lg0, 1);
        lg1 += __shfl_xor_sync(0xffffffffu, lg1, 1);
        lg2 += __shfl_xor_sync(0xffffffffu, lg2, 1);
        lg3 += __shfl_xor_sync(0xffffffffu, lg3, 1);

        float m = fmaxf(fmaxf(lg0, lg1), fmaxf(lg2, lg3));
        float w0 = __expf(lg0 - m);
        float w1 = __expf(lg1 - m);
        float w2 = __expf(lg2 - m);
        float w3 = __expf(lg3 - m);
        float pd = (w0 + w1) + (w2 + w3);
        float4 pa;
        pa.x = fmaf(w0, xv0.x, w1 * xv1.x) + fmaf(w2, xv2.x, w3 * xv3.x);
        pa.y = fmaf(w0, xv0.y, w1 * xv1.y) + fmaf(w2, xv2.y, w3 * xv3.y);
        pa.z = fmaf(w0, xv0.z, w1 * xv1.z) + fmaf(w2, xv2.z, w3 * xv3.z);
        pa.w = fmaf(w0, xv0.w, w1 * xv1.w) + fmaf(w2, xv2.w, w3 * xv3.w);

        float nm = fmaxf(mx, m);
        float a  = __expf(mx - nm);
        float b  = __expf(m - nm);
        dn = fmaf(dn, a, pd * b);
        ac.x = fmaf(ac.x, a, pa.x * b);
        ac.y = fmaf(ac.y, a, pa.y * b);
        ac.z = fmaf(ac.z, a, pa.z * b);
        ac.w = fmaf(ac.w, a, pa.w * b);
        mx = nm;

        xv0 = xn0; xv1 = xn1; xv2 = xn2; xv3 = xn3;
    }

    for (; j < s1; j++) {
        float4 xv = xl_load(XL16, d_csrsrc[j], lane);
        float lg = edge_logit(xv, xrv, attv);
        lg += __shfl_xor_sync(0xffffffffu, lg, 4);
        lg += __shfl_xor_sync(0xffffffffu, lg, 2);
        lg += __shfl_xor_sync(0xffffffffu, lg, 1);
        float nm = fmaxf(mx, lg);
        float a  = __expf(mx - nm);
        float w  = __expf(lg - nm);
        dn = fmaf(dn, a, w);
        ac.x = fmaf(ac.x, a, w * xv.x);
        ac.y = fmaf(ac.y, a, w * xv.y);
        ac.z = fmaf(ac.z, a, w * xv.z);
        ac.w = fmaf(ac.w, a, w * xv.w);
        mx = nm;
    }
}

__global__ void __launch_bounds__(256) gat_row_kernel(const float* __restrict__ att,
                                                      const float* __restrict__ bias)
{
    // 8 warps -> 4 rows; warp pair (2r, 2r+1) splits row r's edge range
    __shared__ float s_mx[4][32], s_dn[4][32];
    __shared__ float s_ac[4][4][32];

    int w    = threadIdx.x >> 5;
    int lane = threadIdx.x & 31;
    int ridx = w >> 1;            // 0..3 row slot in block
    int half = w & 1;
    int row  = blockIdx.x * 4 + ridx;
    if (row >= GN) return;

    float4 attv = ((const float4*)att)[lane];
    float4 xrv  = ((const float4*)d_xr)[(size_t)row * 32 + lane];

    int e0 = d_rowstart[row], e1 = d_rowstart[row + 1];
    int mid = e0 + ((e1 - e0 + 1) >> 1);
    int s0 = half ? mid : e0;
    int s1 = half ? e1  : mid;

    const uint2* XL16 = (const uint2*)d_xl16;

    float mx, dn; float4 ac;
    gat_half(XL16, s0, s1, lane, xrv, attv, mx, dn, ac);

    if (half) {
        s_mx[ridx][lane] = mx;
        s_dn[ridx][lane] = dn;
        s_ac[ridx][0][lane] = ac.x;
        s_ac[ridx][1][lane] = ac.y;
        s_ac[ridx][2][lane] = ac.z;
        s_ac[ridx][3][lane] = ac.w;
    }
    __syncthreads();
    if (half) return;

    // merge the two halves (lane-wise; both warps share the lane->channel map)
    float mxB = s_mx[ridx][lane];
    float dnB = s_dn[ridx][lane];
    float nm = fmaxf(mx, mxB);
    float a  = __expf(mx - nm);
    float b  = __expf(mxB - nm);
    float dnT = fmaf(dn, a, dnB * b);
    float4 acT;
    acT.x = fmaf(ac.x, a, s_ac[ridx][0][lane] * b);
    acT.y = fmaf(ac.y, a, s_ac[ridx][1][lane] * b);
    acT.z = fmaf(ac.z, a, s_ac[ridx][2][lane] * b);
    acT.w = fmaf(ac.w, a, s_ac[ridx][3][lane] * b);

    float inv = 1.f / dnT;
    float4 bv = ((const float4*)bias)[lane];
    float4 o;
    o.x = fmaxf(fmaf(acT.x, inv, bv.x), 0.f);
    o.y = fmaxf(fmaf(acT.y, inv, bv.y), 0.f);
    o.z = fmaxf(fmaf(acT.z, inv, bv.z), 0.f);
    o.w = fmaxf(fmaf(acT.w, inv, bv.w), 0.f);
    ((float4*)d_h)[(size_t)row * 32 + lane] = o;
}

// ---------------- pooling ----------------
__global__ void zero_pool_kernel() {
    int i = blockIdx.x * blockDim.x + threadIdx.x;
    if (i < GG * 128) d_pool[i] = 0.f;
    if (i < GG) d_cnt[i] = 0.f;
}

__global__ void count_kernel(const void* __restrict__ batch) {
    int i = blockIdx.x * blockDim.x + threadIdx.x;
    if (i >= GN) return;
    int g = edge_at(batch, i, d_is64);
    atomicAdd(&d_cnt[g], 1.f);
}

__global__ void pool_kernel(const void* __restrict__ batch) {
    const int CHUNK = 256;
    int n0 = blockIdx.x * CHUNK;
    int n1 = n0 + CHUNK; if (n1 > GN) n1 = GN;
    int col = threadIdx.x;
    int is64 = d_is64;
    int curg = -1;
    float acc = 0.f;
    for (int n = n0; n < n1; n++) {
        int g = edge_at(batch, n, is64);
        if (g != curg) {
            if (curg >= 0) atomicAdd(&d_pool[curg * 128 + col], acc);
            curg = g; acc = 0.f;
        }
        acc += d_h[(size_t)n * 128 + col];
    }
    if (curg >= 0) atomicAdd(&d_pool[curg * 128 + col], acc);
}

// ---------------- classifier ----------------
__global__ void classifier_kernel(
    const float* __restrict__ Wc1, const float* __restrict__ bc1,
    const float* __restrict__ Wc2, const float* __restrict__ bc2,
    float* __restrict__ out)
{
    int g = threadIdx.x;
    if (g >= GG) return;
    float inv = 1.f / fmaxf(d_cnt[g], 1.f);
    float z[8];
    #pragma unroll
    for (int j = 0; j < 8; j++) {
        float s = 0.f;
        for (int k = 0; k < 128; k++)
            s += d_pool[g * 128 + k] * Wc1[j * 128 + k];
        s = s * inv + bc1[j];
        z[j] = fmaxf(s, 0.f);
    }
    float o = bc2[0];
    #pragma unroll
    for (int j = 0; j < 8; j++) o += z[j] * Wc2[j];
    out[g] = o;
}

// ---------------- launch ----------------
extern "C" void kernel_launch(void* const* d_in, const int* in_sizes, int n_in,
                              void* d_out, int out_size) {
    const float* x     = (const float*)d_in[0];
    const void*  ei    = d_in[1];
    const void*  batch = d_in[2];
    const float* Wl0 = (const float*)d_in[3];
    const float* bl0 = (const float*)d_in[4];
    const float* Wr0 = (const float*)d_in[5];
    const float* br0 = (const float*)d_in[6];
    const float* at0 = (const float*)d_in[7];
    const float* bi0 = (const float*)d_in[8];
    const float* Wl1 = (const float*)d_in[9];
    const float* bl1 = (const float*)d_in[10];
    const float* Wr1 = (const float*)d_in[11];
    const float* br1 = (const float*)d_in[12];
    const float* at1 = (const float*)d_in[13];
    const float* bi1 = (const float*)d_in[14];
    const float* Wc1 = (const float*)d_in[15];
    const float* bc1 = (const float*)d_in[16];
    const float* Wc2 = (const float*)d_in[17];
    const float* bc2 = (const float*)d_in[18];
    float* out = (float*)d_out;

    const dim3 GEMM_GRID((GN + 127) / 128, 2);

    detect_kernel<<<1, 32>>>((const int*)ei);                 // 1
    zero_cnt_kernel<<<(GN + 255) / 256, 256>>>();             // 2
    hist_kernel<<<(EP + 255) / 256, 256>>>(ei);               // 3
    gemm_kernel<<<GEMM_GRID, 256>>>(x, Wl0, bl0, Wr0, br0, 0);// 4 (profiled)
    chunk_sum_kernel<<<NCH, 256>>>();                         // 5
    tops_kernel<<<1, 128>>>();                                // 6 (parallel scan)
    scan_apply_kernel<<<NCH, 512>>>();                        // 7
    scatter_kernel<<<(EP + 255) / 256, 256>>>(ei);            // 8

    gat_row_kernel<<<(GN + 3) / 4, 256>>>(at0, bi0);
    gemm_kernel<<<GEMM_GRID, 256>>>(x, Wl1, bl1, Wr1, br1, 1);
    gat_row_kernel<<<(GN + 3) / 4, 256>>>(at1, bi1);

    zero_pool_kernel<<<(GG * 128 + 255) / 256, 256>>>();
    count_kernel<<<(GN + 255) / 256, 256>>>(batch);
    pool_kernel<<<(GN + 255) / 256, 128>>>(batch);
    classifier_kernel<<<1, 64>>>(Wc1, bc1, Wc2, bc2, out);
}